// round 1
// baseline (speedup 1.0000x reference)
#include <cuda_runtime.h>

#define BB 8
#define NN 1024
#define KK 20
#define CAT 512
#define O5 1024

// -------- static device workspaces (no allocation allowed) --------
__device__ float g_f0[BB * NN * 4];            // layer-1 input, point-major, padded
__device__ float g_cat[BB * NN * CAT];         // x1|x2|x3|x4 point-major
__device__ float g_xx[BB * NN];
__device__ float g_nd[BB * NN * NN];           // neg pairwise distances (32MB)
__device__ int   g_idx[BB * NN * KK];
__device__ float g_v[BB * NN * 256];           // Wa @ x    (point-major, stride O)
__device__ float g_u[BB * NN * 256];           // (Wb-Wa)@x
__device__ float g_wa[128 * 256];              // W transposed: [c][o]
__device__ float g_wu[128 * 256];
__device__ float g_maxv[BB * NN * 256];
__device__ float g_minv[BB * NN * 256];
__device__ float g_sum[O5];
__device__ float g_sq[O5];
__device__ float g_pmax[BB * O5 * 4];
__device__ float g_pmin[BB * O5 * 4];
__device__ float g_scale[256];
__device__ float g_bias[256];

__device__ __forceinline__ const float* featPtr(int src, int off) {
    return src ? (g_cat + off) : g_f0;
}

// -------- transpose x (B,3,N) -> (B,N,4) --------
__global__ void prep0(const float* __restrict__ x) {
    int t = blockIdx.x * blockDim.x + threadIdx.x;
    if (t >= BB * NN) return;
    int b = t / NN, n = t % NN;
    float* d = g_f0 + (size_t)t * 4;
    d[0] = x[(b * 3 + 0) * NN + n];
    d[1] = x[(b * 3 + 1) * NN + n];
    d[2] = x[(b * 3 + 2) * NN + n];
    d[3] = 0.f;
}

// -------- per-point squared norm (same accumulation order as Gram GEMM) --------
__global__ void xx_kernel(int src, int off, int stride, int C) {
    int t = blockIdx.x * blockDim.x + threadIdx.x;
    if (t >= BB * NN) return;
    const float* f = featPtr(src, off) + (size_t)t * stride;
    float a = 0.f;
    for (int c = 0; c < C; c++) a = fmaf(f[c], f[c], a);
    g_xx[t] = a;
}

// -------- neg pairwise distance Gram GEMM: 64x64 tile, 4x4 micro --------
__global__ void kd_kernel(int src, int off, int stride, int C) {
    __shared__ float As[32 * 68];
    __shared__ float Bs[32 * 68];
    int b = blockIdx.z;
    int nb = blockIdx.y * 64, mb = blockIdx.x * 64;
    int tid = threadIdx.x;
    int tx = tid & 15, ty = tid >> 4;
    const float* fb = featPtr(src, off) + (size_t)b * NN * stride;

    float acc[4][4];
#pragma unroll
    for (int i = 0; i < 4; i++)
#pragma unroll
        for (int j = 0; j < 4; j++) acc[i][j] = 0.f;

    int nchunk = (C + 31) >> 5;
    for (int cc = 0; cc < nchunk; cc++) {
        for (int l = tid; l < 2048; l += 256) {
            int c = l & 31, r = l >> 5;
            int cg = (cc << 5) + c;
            float va = 0.f, vb = 0.f;
            if (cg < C) {
                va = fb[(size_t)(nb + r) * stride + cg];
                vb = fb[(size_t)(mb + r) * stride + cg];
            }
            As[c * 68 + r] = va;
            Bs[c * 68 + r] = vb;
        }
        __syncthreads();
#pragma unroll
        for (int c = 0; c < 32; c++) {
            float4 a4 = *(const float4*)&As[c * 68 + ty * 4];
            float4 b4 = *(const float4*)&Bs[c * 68 + tx * 4];
            float av[4] = {a4.x, a4.y, a4.z, a4.w};
            float bw[4] = {b4.x, b4.y, b4.z, b4.w};
#pragma unroll
            for (int i = 0; i < 4; i++)
#pragma unroll
                for (int j = 0; j < 4; j++) acc[i][j] = fmaf(av[i], bw[j], acc[i][j]);
        }
        __syncthreads();
    }
    const float* xxb = g_xx + b * NN;
    float xn[4], xm[4];
#pragma unroll
    for (int i = 0; i < 4; i++) xn[i] = xxb[nb + ty * 4 + i];
#pragma unroll
    for (int j = 0; j < 4; j++) xm[j] = xxb[mb + tx * 4 + j];
    float* nd = g_nd + (size_t)b * NN * NN;
#pragma unroll
    for (int i = 0; i < 4; i++)
#pragma unroll
        for (int j = 0; j < 4; j++)
            nd[(size_t)(nb + ty * 4 + i) * NN + (mb + tx * 4 + j)] =
                2.f * acc[i][j] - xn[i] - xm[j];
}

// -------- top-20 per row: iterative argmax, tie -> lowest index --------
__global__ void topk_kernel() {
    __shared__ float sd[NN];
    __shared__ float rv[8];
    __shared__ int   ri[8];
    int n = blockIdx.x, b = blockIdx.y;
    int tid = threadIdx.x;
    const float* row = g_nd + ((size_t)b * NN + n) * NN;
    for (int i = tid; i < NN; i += 256) sd[i] = row[i];
    __syncthreads();
    int* out = g_idx + (b * NN + n) * KK;
    for (int k = 0; k < KK; k++) {
        float bv = -3.0e38f;
        int bi = NN;
        for (int i = tid; i < NN; i += 256) {
            float v = sd[i];
            if (v > bv) { bv = v; bi = i; }
        }
#pragma unroll
        for (int offw = 16; offw; offw >>= 1) {
            float ov = __shfl_down_sync(0xffffffffu, bv, offw);
            int   oi = __shfl_down_sync(0xffffffffu, bi, offw);
            if (ov > bv || (ov == bv && oi < bi)) { bv = ov; bi = oi; }
        }
        if ((tid & 31) == 0) { rv[tid >> 5] = bv; ri[tid >> 5] = bi; }
        __syncthreads();
        if (tid == 0) {
            for (int w = 1; w < 8; w++)
                if (rv[w] > bv || (rv[w] == bv && ri[w] < bi)) { bv = rv[w]; bi = ri[w]; }
            out[k] = bi;
            sd[bi] = -3.0e38f;
        }
        __syncthreads();
    }
}

// -------- transpose / split W: g_wa[c][o]=W[o][c], g_wu[c][o]=W[o][C+c]-W[o][c] --------
__global__ void prepW(const float* __restrict__ W, int C, int O) {
    int t = blockIdx.x * blockDim.x + threadIdx.x;
    if (t >= C * O) return;
    int c = t / O, o = t % O;
    float wa = W[o * (2 * C) + c];
    float wb = W[o * (2 * C) + C + c];
    g_wa[c * O + o] = wa;
    g_wu[c * O + o] = wb - wa;
}

// -------- v = Wa@x, u = (Wb-Wa)@x ; block = O threads, 16 points/block --------
__global__ void k2_kernel(int src, int off, int stride, int C, int O) {
    __shared__ float sf[16 * 128];
    int b = blockIdx.y;
    int n0 = blockIdx.x * 16;
    int o = threadIdx.x;
    const float* fb = featPtr(src, off) + ((size_t)b * NN + n0) * stride;
    for (int l = o; l < 16 * C; l += O) {
        int p = l / C, c = l % C;
        sf[p * C + c] = fb[(size_t)p * stride + c];
    }
    __syncthreads();
    float va[16], vu[16];
#pragma unroll
    for (int p = 0; p < 16; p++) { va[p] = 0.f; vu[p] = 0.f; }
    for (int c = 0; c < C; c++) {
        float wa = g_wa[c * O + o];
        float wu = g_wu[c * O + o];
#pragma unroll
        for (int p = 0; p < 16; p++) {
            float f = sf[p * C + c];
            va[p] = fmaf(wa, f, va[p]);
            vu[p] = fmaf(wu, f, vu[p]);
        }
    }
#pragma unroll
    for (int p = 0; p < 16; p++) {
        size_t idx = ((size_t)b * NN + n0 + p) * O + o;
        g_v[idx] = va[p];
        g_u[idx] = vu[p];
    }
}

__global__ void zero_sums() {
    int t = threadIdx.x;
    g_sum[t] = 0.f;
    g_sq[t] = 0.f;
}

// -------- gather + k-reduce + channel stats --------
__global__ void k3_kernel(int O) {
    int b = blockIdx.y;
    int n0 = blockIdx.x * 16;
    int o = threadIdx.x;
    size_t base = (size_t)b * NN;
    float s = 0.f, q = 0.f;
    for (int p = 0; p < 16; p++) {
        int n = n0 + p;
        const int* id = g_idx + (base + n) * KK;
        float uu = g_u[(base + n) * O + o];
        float mx = -3.0e38f, mn = 3.0e38f;
#pragma unroll
        for (int k = 0; k < KK; k++) {
            int j = id[k];
            float y = g_v[(base + j) * O + o] + uu;
            mx = fmaxf(mx, y);
            mn = fminf(mn, y);
            s += y;
            q = fmaf(y, y, q);
        }
        g_maxv[(base + n) * O + o] = mx;
        g_minv[(base + n) * O + o] = mn;
    }
    atomicAdd(&g_sum[o], s);
    atomicAdd(&g_sq[o], q);
}

// -------- BN finalize per channel --------
__global__ void k4a(const float* __restrict__ gam, const float* __restrict__ bet,
                    float cnt, int O) {
    int o = threadIdx.x;
    if (o >= O) return;
    float m = g_sum[o] / cnt;
    float var = g_sq[o] / cnt - m * m;
    float sc = gam[o] * rsqrtf(var + 1e-5f);
    g_scale[o] = sc;
    g_bias[o] = bet[o] - m * sc;
}

// -------- apply BN + lrelu on the k-pooled value, write into cat --------
__global__ void k4b(int O, int coff) {
    int t = blockIdx.x * blockDim.x + threadIdx.x;
    if (t >= BB * NN * O) return;
    int o = t % O;
    size_t pn = t / O;
    float sc = g_scale[o], bi = g_bias[o];
    float sel = (sc >= 0.f) ? g_maxv[t] : g_minv[t];
    float y = fmaf(sc, sel, bi);
    g_cat[pn * CAT + coff + o] = (y >= 0.f) ? y : 0.2f * y;
}

// -------- final conv1d GEMM (1024x512 @ cat^T) + fused n-stats --------
__global__ void f1_kernel(const float* __restrict__ W5) {
    __shared__ float Ws[32 * 68];
    __shared__ float Cs[32 * 68];
    __shared__ float rbuf[64 * 16];
    int ob = blockIdx.x * 64;
    int nsb = blockIdx.y * 256;
    int b = blockIdx.z;
    int tid = threadIdx.x;
    int tx = tid & 15, ty = tid >> 4;

    float tmax[4], tmin[4], tsum[4], tsq[4];
#pragma unroll
    for (int i = 0; i < 4; i++) { tmax[i] = -3.0e38f; tmin[i] = 3.0e38f; tsum[i] = 0.f; tsq[i] = 0.f; }

    const float* cb = g_cat + (size_t)b * NN * CAT;

    for (int nt = 0; nt < 4; nt++) {
        int nb = nsb + nt * 64;
        float acc[4][4];
#pragma unroll
        for (int i = 0; i < 4; i++)
#pragma unroll
            for (int j = 0; j < 4; j++) acc[i][j] = 0.f;
        for (int cc = 0; cc < 16; cc++) {
            for (int l = tid; l < 2048; l += 256) {
                int c = l & 31, r = l >> 5;
                Ws[c * 68 + r] = W5[(size_t)(ob + r) * 512 + (cc << 5) + c];
                Cs[c * 68 + r] = cb[(size_t)(nb + r) * 512 + (cc << 5) + c];
            }
            __syncthreads();
#pragma unroll
            for (int c = 0; c < 32; c++) {
                float4 a4 = *(const float4*)&Ws[c * 68 + ty * 4];
                float4 b4 = *(const float4*)&Cs[c * 68 + tx * 4];
                float av[4] = {a4.x, a4.y, a4.z, a4.w};
                float bw[4] = {b4.x, b4.y, b4.z, b4.w};
#pragma unroll
                for (int i = 0; i < 4; i++)
#pragma unroll
                    for (int j = 0; j < 4; j++) acc[i][j] = fmaf(av[i], bw[j], acc[i][j]);
            }
            __syncthreads();
        }
#pragma unroll
        for (int i = 0; i < 4; i++)
#pragma unroll
            for (int j = 0; j < 4; j++) {
                float v = acc[i][j];
                tmax[i] = fmaxf(tmax[i], v);
                tmin[i] = fminf(tmin[i], v);
                tsum[i] += v;
                tsq[i] = fmaf(v, v, tsq[i]);
            }
    }

    // reduce across tx (16 threads per o)
#pragma unroll
    for (int i = 0; i < 4; i++) rbuf[(ty * 4 + i) * 16 + tx] = tmax[i];
    __syncthreads();
    if (tid < 64) {
        float m = -3.0e38f;
        for (int j = 0; j < 16; j++) m = fmaxf(m, rbuf[tid * 16 + j]);
        g_pmax[((size_t)b * O5 + ob + tid) * 4 + blockIdx.y] = m;
    }
    __syncthreads();
#pragma unroll
    for (int i = 0; i < 4; i++) rbuf[(ty * 4 + i) * 16 + tx] = tmin[i];
    __syncthreads();
    if (tid < 64) {
        float m = 3.0e38f;
        for (int j = 0; j < 16; j++) m = fminf(m, rbuf[tid * 16 + j]);
        g_pmin[((size_t)b * O5 + ob + tid) * 4 + blockIdx.y] = m;
    }
    __syncthreads();
#pragma unroll
    for (int i = 0; i < 4; i++) rbuf[(ty * 4 + i) * 16 + tx] = tsum[i];
    __syncthreads();
    if (tid < 64) {
        float s = 0.f;
        for (int j = 0; j < 16; j++) s += rbuf[tid * 16 + j];
        atomicAdd(&g_sum[ob + tid], s);
    }
    __syncthreads();
#pragma unroll
    for (int i = 0; i < 4; i++) rbuf[(ty * 4 + i) * 16 + tx] = tsq[i];
    __syncthreads();
    if (tid < 64) {
        float s = 0.f;
        for (int j = 0; j < 16; j++) s += rbuf[tid * 16 + j];
        atomicAdd(&g_sq[ob + tid], s);
    }
}

// -------- final BN + lrelu + max over n --------
__global__ void f2_kernel(const float* __restrict__ g5, const float* __restrict__ b5,
                          float* __restrict__ out) {
    int t = blockIdx.x * blockDim.x + threadIdx.x;
    if (t >= BB * O5) return;
    int b = t / O5, o = t % O5;
    float m = g_sum[o] / 8192.f;
    float var = g_sq[o] / 8192.f - m * m;
    float sc = g5[o] * rsqrtf(var + 1e-5f);
    float bi = b5[o] - m * sc;
    size_t base = ((size_t)b * O5 + o) * 4;
    float sel;
    if (sc >= 0.f) {
        sel = g_pmax[base];
        for (int i = 1; i < 4; i++) sel = fmaxf(sel, g_pmax[base + i]);
    } else {
        sel = g_pmin[base];
        for (int i = 1; i < 4; i++) sel = fminf(sel, g_pmin[base + i]);
    }
    float y = fmaf(sc, sel, bi);
    out[t] = (y >= 0.f) ? y : 0.2f * y;
}

extern "C" void kernel_launch(void* const* d_in, const int* in_sizes, int n_in,
                              void* d_out, int out_size) {
    const float* x  = (const float*)d_in[0];
    const float* Wl[4] = {(const float*)d_in[1], (const float*)d_in[4],
                          (const float*)d_in[7], (const float*)d_in[10]};
    const float* gl[4] = {(const float*)d_in[2], (const float*)d_in[5],
                          (const float*)d_in[8], (const float*)d_in[11]};
    const float* bl[4] = {(const float*)d_in[3], (const float*)d_in[6],
                          (const float*)d_in[9], (const float*)d_in[12]};
    const float* W5 = (const float*)d_in[13];
    const float* g5 = (const float*)d_in[14];
    const float* b5 = (const float*)d_in[15];
    float* out = (float*)d_out;

    prep0<<<32, 256>>>(x);

    const int srcA[4]  = {0, 1, 1, 1};
    const int offA[4]  = {0, 0, 64, 128};
    const int CA[4]    = {3, 64, 64, 128};
    const int OA[4]    = {64, 64, 128, 256};
    const int coffA[4] = {0, 64, 128, 256};

    for (int L = 0; L < 4; L++) {
        int src = srcA[L], off = offA[L], C = CA[L], O = OA[L], coff = coffA[L];
        int stride = src ? CAT : 4;
        xx_kernel<<<32, 256>>>(src, off, stride, C);
        kd_kernel<<<dim3(16, 16, BB), 256>>>(src, off, stride, C);
        topk_kernel<<<dim3(NN, BB), 256>>>();
        prepW<<<(C * O + 255) / 256, 256>>>(Wl[L], C, O);
        k2_kernel<<<dim3(NN / 16, BB), O>>>(src, off, stride, C, O);
        zero_sums<<<1, 1024>>>();
        k3_kernel<<<dim3(NN / 16, BB), O>>>(O);
        k4a<<<1, O>>>(gl[L], bl[L], (float)(BB * NN * KK), O);
        k4b<<<(BB * NN * O + 255) / 256, 256>>>(O, coff);
    }

    zero_sums<<<1, 1024>>>();
    f1_kernel<<<dim3(16, 4, BB), 256>>>(W5);
    f2_kernel<<<32, 256>>>(g5, b5, out);
}

// round 2
// speedup vs baseline: 1.2980x; 1.2980x over previous
#include <cuda_runtime.h>

#define BB 8
#define NN 1024
#define KK 20
#define CAT 512
#define O5 1024

// -------- static device workspaces (no allocation allowed) --------
__device__ float g_f0[BB * NN * 4];            // layer-1 input, point-major, padded
__device__ float g_cat[BB * NN * CAT];         // x1|x2|x3|x4 point-major
__device__ float g_xx[BB * NN];
__device__ float g_nd[BB * NN * NN];           // neg pairwise distances (32MB)
__device__ int   g_idx[BB * NN * KK];
__device__ float g_v[BB * NN * 256];           // Wa @ x    (point-major, stride O)
__device__ float g_u[BB * NN * 256];           // (Wb-Wa)@x
__device__ float g_wa[128 * 256];              // W transposed: [c][o]
__device__ float g_wu[128 * 256];
__device__ float g_maxv[BB * NN * 256];
__device__ float g_minv[BB * NN * 256];
__device__ float g_sum[O5];
__device__ float g_sq[O5];
__device__ float g_pmax[BB * O5 * 4];
__device__ float g_pmin[BB * O5 * 4];
__device__ float g_scale[256];
__device__ float g_bias[256];

__device__ __forceinline__ const float* featPtr(int src, int off) {
    return src ? (g_cat + off) : g_f0;
}

// -------- transpose x (B,3,N) -> (B,N,4) --------
__global__ void prep0(const float* __restrict__ x) {
    int t = blockIdx.x * blockDim.x + threadIdx.x;
    if (t >= BB * NN) return;
    int b = t / NN, n = t % NN;
    float* d = g_f0 + (size_t)t * 4;
    d[0] = x[(b * 3 + 0) * NN + n];
    d[1] = x[(b * 3 + 1) * NN + n];
    d[2] = x[(b * 3 + 2) * NN + n];
    d[3] = 0.f;
}

// -------- per-point squared norm (same accumulation order as Gram GEMM) --------
__global__ void xx_kernel(int src, int off, int stride, int C) {
    int t = blockIdx.x * blockDim.x + threadIdx.x;
    if (t >= BB * NN) return;
    const float* f = featPtr(src, off) + (size_t)t * stride;
    float a = 0.f;
    for (int c = 0; c < C; c++) a = fmaf(f[c], f[c], a);
    g_xx[t] = a;
}

// -------- neg pairwise distance Gram GEMM: 64x64 tile, 4x4 micro --------
__global__ void kd_kernel(int src, int off, int stride, int C) {
    __shared__ float As[32 * 68];
    __shared__ float Bs[32 * 68];
    int b = blockIdx.z;
    int nb = blockIdx.y * 64, mb = blockIdx.x * 64;
    int tid = threadIdx.x;
    int tx = tid & 15, ty = tid >> 4;
    const float* fb = featPtr(src, off) + (size_t)b * NN * stride;

    float acc[4][4];
#pragma unroll
    for (int i = 0; i < 4; i++)
#pragma unroll
        for (int j = 0; j < 4; j++) acc[i][j] = 0.f;

    int nchunk = (C + 31) >> 5;
    for (int cc = 0; cc < nchunk; cc++) {
        for (int l = tid; l < 2048; l += 256) {
            int c = l & 31, r = l >> 5;
            int cg = (cc << 5) + c;
            float va = 0.f, vb = 0.f;
            if (cg < C) {
                va = fb[(size_t)(nb + r) * stride + cg];
                vb = fb[(size_t)(mb + r) * stride + cg];
            }
            As[c * 68 + r] = va;
            Bs[c * 68 + r] = vb;
        }
        __syncthreads();
#pragma unroll
        for (int c = 0; c < 32; c++) {
            float4 a4 = *(const float4*)&As[c * 68 + ty * 4];
            float4 b4 = *(const float4*)&Bs[c * 68 + tx * 4];
            float av[4] = {a4.x, a4.y, a4.z, a4.w};
            float bw[4] = {b4.x, b4.y, b4.z, b4.w};
#pragma unroll
            for (int i = 0; i < 4; i++)
#pragma unroll
                for (int j = 0; j < 4; j++) acc[i][j] = fmaf(av[i], bw[j], acc[i][j]);
        }
        __syncthreads();
    }
    const float* xxb = g_xx + b * NN;
    float xn[4], xm[4];
#pragma unroll
    for (int i = 0; i < 4; i++) xn[i] = xxb[nb + ty * 4 + i];
#pragma unroll
    for (int j = 0; j < 4; j++) xm[j] = xxb[mb + tx * 4 + j];
    float* nd = g_nd + (size_t)b * NN * NN;
#pragma unroll
    for (int i = 0; i < 4; i++)
#pragma unroll
        for (int j = 0; j < 4; j++)
            nd[(size_t)(nb + ty * 4 + i) * NN + (mb + tx * 4 + j)] =
                2.f * acc[i][j] - xn[i] - xm[j];
}

// -------- top-20 per row: one warp per row, register-resident --------
// Each lane holds 32 values (row[j*32+lane]) + alive bitmask + cached local
// argmax. Per round: butterfly shfl reduce over lane maxima (tie -> lowest
// global index, matching lax.top_k), winner lane recomputes its local max.
__global__ void topk_kernel() {
    int wid = threadIdx.x >> 5;
    int lane = threadIdx.x & 31;
    int rowg = blockIdx.x * 8 + wid;      // 0 .. BB*NN-1
    const float* row = g_nd + (size_t)rowg * NN;

    float vals[32];
#pragma unroll
    for (int j = 0; j < 32; j++) vals[j] = row[j * 32 + lane];

    unsigned alive = 0xffffffffu;
    float lv = -3.0e38f;
    int li = 0;
#pragma unroll
    for (int j = 0; j < 32; j++) {
        if (vals[j] > lv) { lv = vals[j]; li = j; }
    }

    int myout = 0;
    for (int k = 0; k < KK; k++) {
        float bv = lv;
        int bi = li * 32 + lane;
#pragma unroll
        for (int s = 16; s; s >>= 1) {
            float ov = __shfl_xor_sync(0xffffffffu, bv, s);
            int oi = __shfl_xor_sync(0xffffffffu, bi, s);
            if (ov > bv || (ov == bv && oi < bi)) { bv = ov; bi = oi; }
        }
        if (lane == k) myout = bi;
        if (lane == (bi & 31)) {
            alive &= ~(1u << (bi >> 5));
            lv = -3.0e38f;
            li = 0;
#pragma unroll
            for (int j = 0; j < 32; j++) {
                float v = ((alive >> j) & 1u) ? vals[j] : -3.0e38f;
                if (v > lv) { lv = v; li = j; }
            }
        }
    }
    if (lane < KK) g_idx[rowg * KK + lane] = myout;
}

// -------- transpose / split W: g_wa[c][o]=W[o][c], g_wu[c][o]=W[o][C+c]-W[o][c] --------
__global__ void prepW(const float* __restrict__ W, int C, int O) {
    int t = blockIdx.x * blockDim.x + threadIdx.x;
    if (t >= C * O) return;
    int c = t / O, o = t % O;
    float wa = W[o * (2 * C) + c];
    float wb = W[o * (2 * C) + C + c];
    g_wa[c * O + o] = wa;
    g_wu[c * O + o] = wb - wa;
}

// -------- v = Wa@x, u = (Wb-Wa)@x ; block = O threads, 16 points/block --------
__global__ void k2_kernel(int src, int off, int stride, int C, int O) {
    __shared__ float sf[16 * 128];
    int b = blockIdx.y;
    int n0 = blockIdx.x * 16;
    int o = threadIdx.x;
    const float* fb = featPtr(src, off) + ((size_t)b * NN + n0) * stride;
    for (int l = o; l < 16 * C; l += O) {
        int p = l / C, c = l % C;
        sf[p * C + c] = fb[(size_t)p * stride + c];
    }
    __syncthreads();
    float va[16], vu[16];
#pragma unroll
    for (int p = 0; p < 16; p++) { va[p] = 0.f; vu[p] = 0.f; }
    for (int c = 0; c < C; c++) {
        float wa = g_wa[c * O + o];
        float wu = g_wu[c * O + o];
#pragma unroll
        for (int p = 0; p < 16; p++) {
            float f = sf[p * C + c];
            va[p] = fmaf(wa, f, va[p]);
            vu[p] = fmaf(wu, f, vu[p]);
        }
    }
#pragma unroll
    for (int p = 0; p < 16; p++) {
        size_t idx = ((size_t)b * NN + n0 + p) * O + o;
        g_v[idx] = va[p];
        g_u[idx] = vu[p];
    }
}

__global__ void zero_sums() {
    int t = threadIdx.x;
    g_sum[t] = 0.f;
    g_sq[t] = 0.f;
}

// -------- gather + k-reduce + channel stats --------
__global__ void k3_kernel(int O) {
    int b = blockIdx.y;
    int n0 = blockIdx.x * 16;
    int o = threadIdx.x;
    size_t base = (size_t)b * NN;
    float s = 0.f, q = 0.f;
    for (int p = 0; p < 16; p++) {
        int n = n0 + p;
        const int* id = g_idx + (base + n) * KK;
        float uu = g_u[(base + n) * O + o];
        float mx = -3.0e38f, mn = 3.0e38f;
#pragma unroll
        for (int k = 0; k < KK; k++) {
            int j = id[k];
            float y = g_v[(base + j) * O + o] + uu;
            mx = fmaxf(mx, y);
            mn = fminf(mn, y);
            s += y;
            q = fmaf(y, y, q);
        }
        g_maxv[(base + n) * O + o] = mx;
        g_minv[(base + n) * O + o] = mn;
    }
    atomicAdd(&g_sum[o], s);
    atomicAdd(&g_sq[o], q);
}

// -------- BN finalize per channel --------
__global__ void k4a(const float* __restrict__ gam, const float* __restrict__ bet,
                    float cnt, int O) {
    int o = threadIdx.x;
    if (o >= O) return;
    float m = g_sum[o] / cnt;
    float var = g_sq[o] / cnt - m * m;
    float sc = gam[o] * rsqrtf(var + 1e-5f);
    g_scale[o] = sc;
    g_bias[o] = bet[o] - m * sc;
}

// -------- apply BN + lrelu on the k-pooled value, write into cat --------
__global__ void k4b(int O, int coff) {
    int t = blockIdx.x * blockDim.x + threadIdx.x;
    if (t >= BB * NN * O) return;
    int o = t % O;
    size_t pn = t / O;
    float sc = g_scale[o], bi = g_bias[o];
    float sel = (sc >= 0.f) ? g_maxv[t] : g_minv[t];
    float y = fmaf(sc, sel, bi);
    g_cat[pn * CAT + coff + o] = (y >= 0.f) ? y : 0.2f * y;
}

// -------- final conv1d GEMM (1024x512 @ cat^T) + fused n-stats --------
__global__ void f1_kernel(const float* __restrict__ W5) {
    __shared__ float Ws[32 * 68];
    __shared__ float Cs[32 * 68];
    __shared__ float rbuf[64 * 16];
    int ob = blockIdx.x * 64;
    int nsb = blockIdx.y * 256;
    int b = blockIdx.z;
    int tid = threadIdx.x;
    int tx = tid & 15, ty = tid >> 4;

    float tmax[4], tmin[4], tsum[4], tsq[4];
#pragma unroll
    for (int i = 0; i < 4; i++) { tmax[i] = -3.0e38f; tmin[i] = 3.0e38f; tsum[i] = 0.f; tsq[i] = 0.f; }

    const float* cb = g_cat + (size_t)b * NN * CAT;

    for (int nt = 0; nt < 4; nt++) {
        int nb = nsb + nt * 64;
        float acc[4][4];
#pragma unroll
        for (int i = 0; i < 4; i++)
#pragma unroll
            for (int j = 0; j < 4; j++) acc[i][j] = 0.f;
        for (int cc = 0; cc < 16; cc++) {
            for (int l = tid; l < 2048; l += 256) {
                int c = l & 31, r = l >> 5;
                Ws[c * 68 + r] = W5[(size_t)(ob + r) * 512 + (cc << 5) + c];
                Cs[c * 68 + r] = cb[(size_t)(nb + r) * 512 + (cc << 5) + c];
            }
            __syncthreads();
#pragma unroll
            for (int c = 0; c < 32; c++) {
                float4 a4 = *(const float4*)&Ws[c * 68 + ty * 4];
                float4 b4 = *(const float4*)&Cs[c * 68 + tx * 4];
                float av[4] = {a4.x, a4.y, a4.z, a4.w};
                float bw[4] = {b4.x, b4.y, b4.z, b4.w};
#pragma unroll
                for (int i = 0; i < 4; i++)
#pragma unroll
                    for (int j = 0; j < 4; j++) acc[i][j] = fmaf(av[i], bw[j], acc[i][j]);
            }
            __syncthreads();
        }
#pragma unroll
        for (int i = 0; i < 4; i++)
#pragma unroll
            for (int j = 0; j < 4; j++) {
                float v = acc[i][j];
                tmax[i] = fmaxf(tmax[i], v);
                tmin[i] = fminf(tmin[i], v);
                tsum[i] += v;
                tsq[i] = fmaf(v, v, tsq[i]);
            }
    }

    // reduce across tx (16 threads per o)
#pragma unroll
    for (int i = 0; i < 4; i++) rbuf[(ty * 4 + i) * 16 + tx] = tmax[i];
    __syncthreads();
    if (tid < 64) {
        float m = -3.0e38f;
        for (int j = 0; j < 16; j++) m = fmaxf(m, rbuf[tid * 16 + j]);
        g_pmax[((size_t)b * O5 + ob + tid) * 4 + blockIdx.y] = m;
    }
    __syncthreads();
#pragma unroll
    for (int i = 0; i < 4; i++) rbuf[(ty * 4 + i) * 16 + tx] = tmin[i];
    __syncthreads();
    if (tid < 64) {
        float m = 3.0e38f;
        for (int j = 0; j < 16; j++) m = fminf(m, rbuf[tid * 16 + j]);
        g_pmin[((size_t)b * O5 + ob + tid) * 4 + blockIdx.y] = m;
    }
    __syncthreads();
#pragma unroll
    for (int i = 0; i < 4; i++) rbuf[(ty * 4 + i) * 16 + tx] = tsum[i];
    __syncthreads();
    if (tid < 64) {
        float s = 0.f;
        for (int j = 0; j < 16; j++) s += rbuf[tid * 16 + j];
        atomicAdd(&g_sum[ob + tid], s);
    }
    __syncthreads();
#pragma unroll
    for (int i = 0; i < 4; i++) rbuf[(ty * 4 + i) * 16 + tx] = tsq[i];
    __syncthreads();
    if (tid < 64) {
        float s = 0.f;
        for (int j = 0; j < 16; j++) s += rbuf[tid * 16 + j];
        atomicAdd(&g_sq[ob + tid], s);
    }
}

// -------- final BN + lrelu + max over n --------
__global__ void f2_kernel(const float* __restrict__ g5, const float* __restrict__ b5,
                          float* __restrict__ out) {
    int t = blockIdx.x * blockDim.x + threadIdx.x;
    if (t >= BB * O5) return;
    int b = t / O5, o = t % O5;
    float m = g_sum[o] / 8192.f;
    float var = g_sq[o] / 8192.f - m * m;
    float sc = g5[o] * rsqrtf(var + 1e-5f);
    float bi = b5[o] - m * sc;
    size_t base = ((size_t)b * O5 + o) * 4;
    float sel;
    if (sc >= 0.f) {
        sel = g_pmax[base];
        for (int i = 1; i < 4; i++) sel = fmaxf(sel, g_pmax[base + i]);
    } else {
        sel = g_pmin[base];
        for (int i = 1; i < 4; i++) sel = fminf(sel, g_pmin[base + i]);
    }
    float y = fmaf(sc, sel, bi);
    out[t] = (y >= 0.f) ? y : 0.2f * y;
}

extern "C" void kernel_launch(void* const* d_in, const int* in_sizes, int n_in,
                              void* d_out, int out_size) {
    const float* x  = (const float*)d_in[0];
    const float* Wl[4] = {(const float*)d_in[1], (const float*)d_in[4],
                          (const float*)d_in[7], (const float*)d_in[10]};
    const float* gl[4] = {(const float*)d_in[2], (const float*)d_in[5],
                          (const float*)d_in[8], (const float*)d_in[11]};
    const float* bl[4] = {(const float*)d_in[3], (const float*)d_in[6],
                          (const float*)d_in[9], (const float*)d_in[12]};
    const float* W5 = (const float*)d_in[13];
    const float* g5 = (const float*)d_in[14];
    const float* b5 = (const float*)d_in[15];
    float* out = (float*)d_out;

    prep0<<<32, 256>>>(x);

    const int srcA[4]  = {0, 1, 1, 1};
    const int offA[4]  = {0, 0, 64, 128};
    const int CA[4]    = {3, 64, 64, 128};
    const int OA[4]    = {64, 64, 128, 256};
    const int coffA[4] = {0, 64, 128, 256};

    for (int L = 0; L < 4; L++) {
        int src = srcA[L], off = offA[L], C = CA[L], O = OA[L], coff = coffA[L];
        int stride = src ? CAT : 4;
        xx_kernel<<<32, 256>>>(src, off, stride, C);
        kd_kernel<<<dim3(16, 16, BB), 256>>>(src, off, stride, C);
        topk_kernel<<<BB * NN / 8, 256>>>();
        prepW<<<(C * O + 255) / 256, 256>>>(Wl[L], C, O);
        k2_kernel<<<dim3(NN / 16, BB), O>>>(src, off, stride, C, O);
        zero_sums<<<1, 1024>>>();
        k3_kernel<<<dim3(NN / 16, BB), O>>>(O);
        k4a<<<1, O>>>(gl[L], bl[L], (float)(BB * NN * KK), O);
        k4b<<<(BB * NN * O + 255) / 256, 256>>>(O, coff);
    }

    zero_sums<<<1, 1024>>>();
    f1_kernel<<<dim3(16, 4, BB), 256>>>(W5);
    f2_kernel<<<32, 256>>>(g5, b5, out);
}

// round 3
// speedup vs baseline: 1.5095x; 1.1629x over previous
#include <cuda_runtime.h>

#define BB 8
#define NN 1024
#define KK 20
#define CAT 512
#define O5 1024

typedef unsigned long long ull;

__device__ __forceinline__ ull ffma2(ull a, ull b, ull c) {
    ull d;
    asm("fma.rn.f32x2 %0, %1, %2, %3;" : "=l"(d) : "l"(a), "l"(b), "l"(c));
    return d;
}
__device__ __forceinline__ ull bcast2(float v) {
    ull d;
    asm("mov.b64 %0, {%1, %1};" : "=l"(d) : "f"(v));
    return d;
}
__device__ __forceinline__ void unpack2(ull p, float& lo, float& hi) {
    asm("mov.b64 {%0, %1}, %2;" : "=f"(lo), "=f"(hi) : "l"(p));
}

// -------- static device workspaces (no allocation allowed) --------
__device__ float g_f0[BB * NN * 4];            // layer-1 input, point-major, padded
__device__ float g_cat[BB * NN * CAT];         // x1|x2|x3|x4 point-major
__device__ float g_xx[BB * NN];
__device__ float g_nd[BB * NN * NN];           // neg pairwise distances (32MB)
__device__ int   g_idx[BB * NN * KK];
__device__ float g_v[BB * NN * 256];           // Wa @ x    (point-major, stride O)
__device__ float g_u[BB * NN * 256];           // (Wb-Wa)@x
__device__ float g_wa[128 * 256];              // W transposed: [c][o]
__device__ float g_wu[128 * 256];
__device__ float g_maxv[BB * NN * 256];
__device__ float g_minv[BB * NN * 256];
__device__ float g_sum[O5];
__device__ float g_sq[O5];
__device__ float g_pmax[BB * O5 * 4];
__device__ float g_pmin[BB * O5 * 4];
__device__ float g_scale[256];
__device__ float g_bias[256];

__device__ __forceinline__ const float* featPtr(int src, int off) {
    return src ? (g_cat + off) : g_f0;
}

// -------- transpose x (B,3,N) -> (B,N,4) --------
__global__ void prep0(const float* __restrict__ x) {
    int t = blockIdx.x * blockDim.x + threadIdx.x;
    if (t >= BB * NN) return;
    int b = t / NN, n = t % NN;
    float* d = g_f0 + (size_t)t * 4;
    d[0] = x[(b * 3 + 0) * NN + n];
    d[1] = x[(b * 3 + 1) * NN + n];
    d[2] = x[(b * 3 + 2) * NN + n];
    d[3] = 0.f;
}

// -------- per-point squared norm (same accumulation order as Gram GEMM) --------
__global__ void xx_kernel(int src, int off, int stride, int C) {
    int t = blockIdx.x * blockDim.x + threadIdx.x;
    if (t >= BB * NN) return;
    const float* f = featPtr(src, off) + (size_t)t * stride;
    float a = 0.f;
    for (int c = 0; c < C; c++) a = fmaf(f[c], f[c], a);
    g_xx[t] = a;
}

// -------- neg pairwise distance Gram GEMM: 64x64 tile, 4x4 micro, f32x2 --------
__global__ void kd_kernel(int src, int off, int stride, int C) {
    __shared__ float As[32 * 68];
    __shared__ float Bs[32 * 68];
    int b = blockIdx.z;
    int nb = blockIdx.y * 64, mb = blockIdx.x * 64;
    int tid = threadIdx.x;
    int tx = tid & 15, ty = tid >> 4;
    const float* fb = featPtr(src, off) + (size_t)b * NN * stride;

    ull acc2[4][2];
#pragma unroll
    for (int i = 0; i < 4; i++) { acc2[i][0] = 0ull; acc2[i][1] = 0ull; }

    int nchunk = (C + 31) >> 5;
    for (int cc = 0; cc < nchunk; cc++) {
        for (int l = tid; l < 2048; l += 256) {
            int c = l & 31, r = l >> 5;
            int cg = (cc << 5) + c;
            float va = 0.f, vb = 0.f;
            if (cg < C) {
                va = fb[(size_t)(nb + r) * stride + cg];
                vb = fb[(size_t)(mb + r) * stride + cg];
            }
            As[c * 68 + r] = va;
            Bs[c * 68 + r] = vb;
        }
        __syncthreads();
#pragma unroll
        for (int c = 0; c < 32; c++) {
            float4 a4 = *(const float4*)&As[c * 68 + ty * 4];
            const ull* bp = (const ull*)&Bs[c * 68 + tx * 4];
            ull b2lo = bp[0], b2hi = bp[1];
            ull ap[4] = {bcast2(a4.x), bcast2(a4.y), bcast2(a4.z), bcast2(a4.w)};
#pragma unroll
            for (int i = 0; i < 4; i++) {
                acc2[i][0] = ffma2(ap[i], b2lo, acc2[i][0]);
                acc2[i][1] = ffma2(ap[i], b2hi, acc2[i][1]);
            }
        }
        __syncthreads();
    }
    const float* xxb = g_xx + b * NN;
    float xn[4], xm[4];
#pragma unroll
    for (int i = 0; i < 4; i++) xn[i] = xxb[nb + ty * 4 + i];
#pragma unroll
    for (int j = 0; j < 4; j++) xm[j] = xxb[mb + tx * 4 + j];
    float* nd = g_nd + (size_t)b * NN * NN;
#pragma unroll
    for (int i = 0; i < 4; i++) {
        float a0, a1, a2, a3;
        unpack2(acc2[i][0], a0, a1);
        unpack2(acc2[i][1], a2, a3);
        float ac[4] = {a0, a1, a2, a3};
        float* ndr = nd + (size_t)(nb + ty * 4 + i) * NN + mb + tx * 4;
#pragma unroll
        for (int j = 0; j < 4; j++)
            ndr[j] = 2.f * ac[j] - xn[i] - xm[j];
    }
}

// -------- top-20 per row: one warp per row, register-resident, quartered --------
// Each lane holds 32 values; per-quarter (8-value) cached argmax. Per round:
// butterfly shfl reduce over lane maxima (tie -> lowest global index, matching
// lax.top_k), winner lane rescans only its affected quarter.
__global__ void topk_kernel() {
    int wid = threadIdx.x >> 5;
    int lane = threadIdx.x & 31;
    int rowg = blockIdx.x * 8 + wid;      // 0 .. BB*NN-1
    const float* row = g_nd + (size_t)rowg * NN;

    float vals[32];
#pragma unroll
    for (int j = 0; j < 32; j++) vals[j] = row[j * 32 + lane];

    unsigned alive = 0xffffffffu;
    float qv0, qv1, qv2, qv3;
    int qj0, qj1, qj2, qj3;

#define RESCANQ(Q, QV, QJ)                                            \
    {                                                                 \
        QV = -3.0e38f; QJ = (Q) * 8;                                  \
        _Pragma("unroll")                                             \
        for (int j0 = 0; j0 < 8; j0++) {                              \
            int j = (Q) * 8 + j0;                                     \
            float v = ((alive >> j) & 1u) ? vals[j] : -3.0e38f;       \
            if (v > QV) { QV = v; QJ = j; }                           \
        }                                                             \
    }

    RESCANQ(0, qv0, qj0)
    RESCANQ(1, qv1, qj1)
    RESCANQ(2, qv2, qj2)
    RESCANQ(3, qv3, qj3)

    float lv = qv0; int li = qj0;
    if (qv1 > lv) { lv = qv1; li = qj1; }
    if (qv2 > lv) { lv = qv2; li = qj2; }
    if (qv3 > lv) { lv = qv3; li = qj3; }

    int myout = 0;
    for (int k = 0; k < KK; k++) {
        float bv = lv;
        int bi = li * 32 + lane;
#pragma unroll
        for (int s = 16; s; s >>= 1) {
            float ov = __shfl_xor_sync(0xffffffffu, bv, s);
            int oi = __shfl_xor_sync(0xffffffffu, bi, s);
            if (ov > bv || (ov == bv && oi < bi)) { bv = ov; bi = oi; }
        }
        if (lane == k) myout = bi;
        if (lane == (bi & 31)) {
            int jrem = bi >> 5;
            alive &= ~(1u << jrem);
            int q = jrem >> 3;
            if (q == 0)      RESCANQ(0, qv0, qj0)
            else if (q == 1) RESCANQ(1, qv1, qj1)
            else if (q == 2) RESCANQ(2, qv2, qj2)
            else             RESCANQ(3, qv3, qj3)
            lv = qv0; li = qj0;
            if (qv1 > lv) { lv = qv1; li = qj1; }
            if (qv2 > lv) { lv = qv2; li = qj2; }
            if (qv3 > lv) { lv = qv3; li = qj3; }
        }
    }
    if (lane < KK) g_idx[rowg * KK + lane] = myout;
#undef RESCANQ
}

// -------- transpose / split W: g_wa[c][o]=W[o][c], g_wu[c][o]=W[o][C+c]-W[o][c] --------
__global__ void prepW(const float* __restrict__ W, int C, int O) {
    int t = blockIdx.x * blockDim.x + threadIdx.x;
    if (t >= C * O) return;
    int c = t / O, o = t % O;
    float wa = W[o * (2 * C) + c];
    float wb = W[o * (2 * C) + C + c];
    g_wa[c * O + o] = wa;
    g_wu[c * O + o] = wb - wa;
}

// -------- v = Wa@x, u = (Wb-Wa)@x ; block = O threads, 16 points/block --------
__global__ void k2_kernel(int src, int off, int stride, int C, int O) {
    __shared__ float sf[16 * 128];
    int b = blockIdx.y;
    int n0 = blockIdx.x * 16;
    int o = threadIdx.x;
    const float* fb = featPtr(src, off) + ((size_t)b * NN + n0) * stride;
    for (int l = o; l < 16 * C; l += O) {
        int p = l / C, c = l % C;
        sf[p * C + c] = fb[(size_t)p * stride + c];
    }
    __syncthreads();
    float va[16], vu[16];
#pragma unroll
    for (int p = 0; p < 16; p++) { va[p] = 0.f; vu[p] = 0.f; }
    for (int c = 0; c < C; c++) {
        float wa = g_wa[c * O + o];
        float wu = g_wu[c * O + o];
#pragma unroll
        for (int p = 0; p < 16; p++) {
            float f = sf[p * C + c];
            va[p] = fmaf(wa, f, va[p]);
            vu[p] = fmaf(wu, f, vu[p]);
        }
    }
#pragma unroll
    for (int p = 0; p < 16; p++) {
        size_t idx = ((size_t)b * NN + n0 + p) * O + o;
        g_v[idx] = va[p];
        g_u[idx] = vu[p];
    }
}

__global__ void zero_sums() {
    int t = threadIdx.x;
    g_sum[t] = 0.f;
    g_sq[t] = 0.f;
}

// -------- gather + k-reduce + channel stats --------
__global__ void k3_kernel(int O) {
    int b = blockIdx.y;
    int n0 = blockIdx.x * 16;
    int o = threadIdx.x;
    size_t base = (size_t)b * NN;
    float s = 0.f, q = 0.f;
    for (int p = 0; p < 16; p++) {
        int n = n0 + p;
        const int* id = g_idx + (base + n) * KK;
        float uu = g_u[(base + n) * O + o];
        float mx = -3.0e38f, mn = 3.0e38f;
#pragma unroll
        for (int k = 0; k < KK; k++) {
            int j = id[k];
            float y = g_v[(base + j) * O + o] + uu;
            mx = fmaxf(mx, y);
            mn = fminf(mn, y);
            s += y;
            q = fmaf(y, y, q);
        }
        g_maxv[(base + n) * O + o] = mx;
        g_minv[(base + n) * O + o] = mn;
    }
    atomicAdd(&g_sum[o], s);
    atomicAdd(&g_sq[o], q);
}

// -------- BN finalize per channel --------
__global__ void k4a(const float* __restrict__ gam, const float* __restrict__ bet,
                    float cnt, int O) {
    int o = threadIdx.x;
    if (o >= O) return;
    float m = g_sum[o] / cnt;
    float var = g_sq[o] / cnt - m * m;
    float sc = gam[o] * rsqrtf(var + 1e-5f);
    g_scale[o] = sc;
    g_bias[o] = bet[o] - m * sc;
}

// -------- apply BN + lrelu on the k-pooled value, write into cat --------
__global__ void k4b(int O, int coff) {
    int t = blockIdx.x * blockDim.x + threadIdx.x;
    if (t >= BB * NN * O) return;
    int o = t % O;
    size_t pn = t / O;
    float sc = g_scale[o], bi = g_bias[o];
    float sel = (sc >= 0.f) ? g_maxv[t] : g_minv[t];
    float y = fmaf(sc, sel, bi);
    g_cat[pn * CAT + coff + o] = (y >= 0.f) ? y : 0.2f * y;
}

// -------- final conv1d GEMM (1024x512 @ cat^T) + fused n-stats, f32x2 --------
__global__ void f1_kernel(const float* __restrict__ W5) {
    __shared__ float Ws[32 * 68];
    __shared__ float Cs[32 * 68];
    __shared__ float rbuf[64 * 16];
    int ob = blockIdx.x * 64;
    int nsb = blockIdx.y * 256;
    int b = blockIdx.z;
    int tid = threadIdx.x;
    int tx = tid & 15, ty = tid >> 4;

    float tmax[4], tmin[4], tsum[4], tsq[4];
#pragma unroll
    for (int i = 0; i < 4; i++) { tmax[i] = -3.0e38f; tmin[i] = 3.0e38f; tsum[i] = 0.f; tsq[i] = 0.f; }

    const float* cb = g_cat + (size_t)b * NN * CAT;

    for (int nt = 0; nt < 4; nt++) {
        int nb = nsb + nt * 64;
        ull acc2[4][2];
#pragma unroll
        for (int i = 0; i < 4; i++) { acc2[i][0] = 0ull; acc2[i][1] = 0ull; }
        for (int cc = 0; cc < 16; cc++) {
            for (int l = tid; l < 2048; l += 256) {
                int c = l & 31, r = l >> 5;
                Ws[c * 68 + r] = W5[(size_t)(ob + r) * 512 + (cc << 5) + c];
                Cs[c * 68 + r] = cb[(size_t)(nb + r) * 512 + (cc << 5) + c];
            }
            __syncthreads();
#pragma unroll
            for (int c = 0; c < 32; c++) {
                float4 a4 = *(const float4*)&Ws[c * 68 + ty * 4];
                const ull* bp = (const ull*)&Cs[c * 68 + tx * 4];
                ull b2lo = bp[0], b2hi = bp[1];
                ull ap[4] = {bcast2(a4.x), bcast2(a4.y), bcast2(a4.z), bcast2(a4.w)};
#pragma unroll
                for (int i = 0; i < 4; i++) {
                    acc2[i][0] = ffma2(ap[i], b2lo, acc2[i][0]);
                    acc2[i][1] = ffma2(ap[i], b2hi, acc2[i][1]);
                }
            }
            __syncthreads();
        }
#pragma unroll
        for (int i = 0; i < 4; i++) {
            float a0, a1, a2, a3;
            unpack2(acc2[i][0], a0, a1);
            unpack2(acc2[i][1], a2, a3);
            float ac[4] = {a0, a1, a2, a3};
#pragma unroll
            for (int j = 0; j < 4; j++) {
                float v = ac[j];
                tmax[i] = fmaxf(tmax[i], v);
                tmin[i] = fminf(tmin[i], v);
                tsum[i] += v;
                tsq[i] = fmaf(v, v, tsq[i]);
            }
        }
    }

    // reduce across tx (16 threads per o)
#pragma unroll
    for (int i = 0; i < 4; i++) rbuf[(ty * 4 + i) * 16 + tx] = tmax[i];
    __syncthreads();
    if (tid < 64) {
        float m = -3.0e38f;
        for (int j = 0; j < 16; j++) m = fmaxf(m, rbuf[tid * 16 + j]);
        g_pmax[((size_t)b * O5 + ob + tid) * 4 + blockIdx.y] = m;
    }
    __syncthreads();
#pragma unroll
    for (int i = 0; i < 4; i++) rbuf[(ty * 4 + i) * 16 + tx] = tmin[i];
    __syncthreads();
    if (tid < 64) {
        float m = 3.0e38f;
        for (int j = 0; j < 16; j++) m = fminf(m, rbuf[tid * 16 + j]);
        g_pmin[((size_t)b * O5 + ob + tid) * 4 + blockIdx.y] = m;
    }
    __syncthreads();
#pragma unroll
    for (int i = 0; i < 4; i++) rbuf[(ty * 4 + i) * 16 + tx] = tsum[i];
    __syncthreads();
    if (tid < 64) {
        float s = 0.f;
        for (int j = 0; j < 16; j++) s += rbuf[tid * 16 + j];
        atomicAdd(&g_sum[ob + tid], s);
    }
    __syncthreads();
#pragma unroll
    for (int i = 0; i < 4; i++) rbuf[(ty * 4 + i) * 16 + tx] = tsq[i];
    __syncthreads();
    if (tid < 64) {
        float s = 0.f;
        for (int j = 0; j < 16; j++) s += rbuf[tid * 16 + j];
        atomicAdd(&g_sq[ob + tid], s);
    }
}

// -------- final BN + lrelu + max over n --------
__global__ void f2_kernel(const float* __restrict__ g5, const float* __restrict__ b5,
                          float* __restrict__ out) {
    int t = blockIdx.x * blockDim.x + threadIdx.x;
    if (t >= BB * O5) return;
    int b = t / O5, o = t % O5;
    float m = g_sum[o] / 8192.f;
    float var = g_sq[o] / 8192.f - m * m;
    float sc = g5[o] * rsqrtf(var + 1e-5f);
    float bi = b5[o] - m * sc;
    size_t base = ((size_t)b * O5 + o) * 4;
    float sel;
    if (sc >= 0.f) {
        sel = g_pmax[base];
        for (int i = 1; i < 4; i++) sel = fmaxf(sel, g_pmax[base + i]);
    } else {
        sel = g_pmin[base];
        for (int i = 1; i < 4; i++) sel = fminf(sel, g_pmin[base + i]);
    }
    float y = fmaf(sc, sel, bi);
    out[t] = (y >= 0.f) ? y : 0.2f * y;
}

extern "C" void kernel_launch(void* const* d_in, const int* in_sizes, int n_in,
                              void* d_out, int out_size) {
    const float* x  = (const float*)d_in[0];
    const float* Wl[4] = {(const float*)d_in[1], (const float*)d_in[4],
                          (const float*)d_in[7], (const float*)d_in[10]};
    const float* gl[4] = {(const float*)d_in[2], (const float*)d_in[5],
                          (const float*)d_in[8], (const float*)d_in[11]};
    const float* bl[4] = {(const float*)d_in[3], (const float*)d_in[6],
                          (const float*)d_in[9], (const float*)d_in[12]};
    const float* W5 = (const float*)d_in[13];
    const float* g5 = (const float*)d_in[14];
    const float* b5 = (const float*)d_in[15];
    float* out = (float*)d_out;

    prep0<<<32, 256>>>(x);

    const int srcA[4]  = {0, 1, 1, 1};
    const int offA[4]  = {0, 0, 64, 128};
    const int CA[4]    = {3, 64, 64, 128};
    const int OA[4]    = {64, 64, 128, 256};
    const int coffA[4] = {0, 64, 128, 256};

    for (int L = 0; L < 4; L++) {
        int src = srcA[L], off = offA[L], C = CA[L], O = OA[L], coff = coffA[L];
        int stride = src ? CAT : 4;
        xx_kernel<<<32, 256>>>(src, off, stride, C);
        kd_kernel<<<dim3(16, 16, BB), 256>>>(src, off, stride, C);
        topk_kernel<<<BB * NN / 8, 256>>>();
        prepW<<<(C * O + 255) / 256, 256>>>(Wl[L], C, O);
        k2_kernel<<<dim3(NN / 16, BB), O>>>(src, off, stride, C, O);
        zero_sums<<<1, 1024>>>();
        k3_kernel<<<dim3(NN / 16, BB), O>>>(O);
        k4a<<<1, O>>>(gl[L], bl[L], (float)(BB * NN * KK), O);
        k4b<<<(BB * NN * O + 255) / 256, 256>>>(O, coff);
    }

    zero_sums<<<1, 1024>>>();
    f1_kernel<<<dim3(16, 4, BB), 256>>>(W5);
    f2_kernel<<<32, 256>>>(g5, b5, out);
}

// round 4
// speedup vs baseline: 1.6383x; 1.0854x over previous
#include <cuda_runtime.h>

#define BB 8
#define NN 1024
#define KK 20
#define CAT 512
#define O5 1024

typedef unsigned long long ull;

__device__ __forceinline__ ull ffma2(ull a, ull b, ull c) {
    ull d;
    asm("fma.rn.f32x2 %0, %1, %2, %3;" : "=l"(d) : "l"(a), "l"(b), "l"(c));
    return d;
}
__device__ __forceinline__ ull bcast2(float v) {
    ull d;
    asm("mov.b64 %0, {%1, %1};" : "=l"(d) : "f"(v));
    return d;
}
__device__ __forceinline__ void unpack2(ull p, float& lo, float& hi) {
    asm("mov.b64 {%0, %1}, %2;" : "=f"(lo), "=f"(hi) : "l"(p));
}

// -------- static device workspaces --------
__device__ float g_f0[BB * NN * 4];
__device__ float g_cat[BB * NN * CAT];
__device__ float g_xx[BB * NN];
__device__ float g_nd[BB * NN * NN];
__device__ int   g_idx[BB * NN * KK];
__device__ float g_v[BB * NN * 256];
__device__ float g_u[BB * NN * 256];
__device__ float g_wa[128 * 256];
__device__ float g_wu[128 * 256];
__device__ float g_maxv[BB * NN * 256];
__device__ float g_minv[BB * NN * 256];
__device__ float g_sum[O5];
__device__ float g_sq[O5];
__device__ float g_pmax[BB * O5 * 8];
__device__ float g_pmin[BB * O5 * 8];
__device__ float g_scale[256];
__device__ float g_bias[256];

__device__ __forceinline__ const float* featPtr(int src, int off) {
    return src ? (g_cat + off) : g_f0;
}

// -------- transpose x (B,3,N) -> (B,N,4) --------
__global__ void prep0(const float* __restrict__ x) {
    int t = blockIdx.x * blockDim.x + threadIdx.x;
    if (t >= BB * NN) return;
    int b = t / NN, n = t % NN;
    float* d = g_f0 + (size_t)t * 4;
    d[0] = x[(b * 3 + 0) * NN + n];
    d[1] = x[(b * 3 + 1) * NN + n];
    d[2] = x[(b * 3 + 2) * NN + n];
    d[3] = 0.f;
}

// -------- fused per-layer prep: xx norms + W split/transpose + zero stats --------
__global__ void prep_layer(const float* __restrict__ W, int src, int off,
                           int stride, int C, int O) {
    int bx = blockIdx.x;
    if (bx < 32) {                       // per-point squared norm
        int t = bx * 256 + threadIdx.x;
        const float* f = featPtr(src, off) + (size_t)t * stride;
        float a = 0.f;
        for (int c = 0; c < C; c++) a = fmaf(f[c], f[c], a);
        g_xx[t] = a;
    } else if (bx < 160) {               // W transpose/split
        int t = (bx - 32) * 256 + threadIdx.x;
        if (t < C * O) {
            int c = t / O, o = t % O;
            float wa = W[o * (2 * C) + c];
            float wb = W[o * (2 * C) + C + c];
            g_wa[c * O + o] = wa;
            g_wu[c * O + o] = wb - wa;
        }
    } else {                             // zero channel stats
        for (int t = threadIdx.x; t < O5; t += 256) {
            g_sum[t] = 0.f;
            g_sq[t] = 0.f;
        }
    }
}

// -------- neg pairwise distance Gram GEMM: 128x128 tile, 8x8 micro, f32x2 --------
__global__ __launch_bounds__(256, 2) void kd_kernel(int src, int off, int stride, int C) {
    __shared__ float Ad[16 * 258];       // duplicated-A: {a,a} pairs per row
    __shared__ float Bs_[16 * 132];
    int b = blockIdx.z;
    int ib = blockIdx.y * 128, jb = blockIdx.x * 128;
    int tid = threadIdx.x;
    int tx = tid & 15, ty = tid >> 4;
    const float* fb = featPtr(src, off) + (size_t)b * NN * stride;

    ull acc[8][4];
#pragma unroll
    for (int i = 0; i < 8; i++)
#pragma unroll
        for (int j = 0; j < 4; j++) acc[i][j] = 0ull;

    int nch = (C + 15) >> 4;
    for (int cc = 0; cc < nch; cc++) {
#pragma unroll
        for (int l0 = 0; l0 < 8; l0++) {
            int l = l0 * 256 + tid;
            int c = l & 15, r = l >> 4;
            int cg = (cc << 4) + c;
            float a = 0.f, bv = 0.f;
            if (cg < C) {
                a = fb[(size_t)(ib + r) * stride + cg];
                bv = fb[(size_t)(jb + r) * stride + cg];
            }
            *(ull*)&Ad[c * 258 + 2 * r] = bcast2(a);
            Bs_[c * 132 + r] = bv;
        }
        __syncthreads();
#pragma unroll
        for (int c = 0; c < 16; c++) {
            const float* arow = &Ad[c * 258 + ty * 16];
            const float* brow = &Bs_[c * 132 + tx * 8];
            ull b0 = *(const ull*)&brow[0];
            ull b1 = *(const ull*)&brow[2];
            ull b2 = *(const ull*)&brow[4];
            ull b3 = *(const ull*)&brow[6];
#pragma unroll
            for (int i = 0; i < 8; i++) {
                ull ap = *(const ull*)&arow[2 * i];
                acc[i][0] = ffma2(ap, b0, acc[i][0]);
                acc[i][1] = ffma2(ap, b1, acc[i][1]);
                acc[i][2] = ffma2(ap, b2, acc[i][2]);
                acc[i][3] = ffma2(ap, b3, acc[i][3]);
            }
        }
        __syncthreads();
    }

    const float* xxb = g_xx + b * NN;
    float xm[8];
#pragma unroll
    for (int j = 0; j < 8; j++) xm[j] = xxb[jb + tx * 8 + j];
    float* nd = g_nd + (size_t)b * NN * NN;
#pragma unroll
    for (int i = 0; i < 8; i++) {
        float xn = xxb[ib + ty * 8 + i];
        float v[8];
#pragma unroll
        for (int j = 0; j < 4; j++) unpack2(acc[i][j], v[2 * j], v[2 * j + 1]);
        float4 o0, o1;
        o0.x = 2.f * v[0] - xn - xm[0];
        o0.y = 2.f * v[1] - xn - xm[1];
        o0.z = 2.f * v[2] - xn - xm[2];
        o0.w = 2.f * v[3] - xn - xm[3];
        o1.x = 2.f * v[4] - xn - xm[4];
        o1.y = 2.f * v[5] - xn - xm[5];
        o1.z = 2.f * v[6] - xn - xm[6];
        o1.w = 2.f * v[7] - xn - xm[7];
        float4* dst = (float4*)(nd + (size_t)(ib + ty * 8 + i) * NN + jb + tx * 8);
        dst[0] = o0;
        dst[1] = o1;
    }
}

// -------- top-20 per row: one warp per row, register-resident, quartered --------
__global__ void topk_kernel() {
    int wid = threadIdx.x >> 5;
    int lane = threadIdx.x & 31;
    int rowg = blockIdx.x * 8 + wid;
    const float* row = g_nd + (size_t)rowg * NN;

    float vals[32];
#pragma unroll
    for (int j = 0; j < 32; j++) vals[j] = row[j * 32 + lane];

    unsigned alive = 0xffffffffu;
    float qv0, qv1, qv2, qv3;
    int qj0, qj1, qj2, qj3;

#define RESCANQ(Q, QV, QJ)                                            \
    {                                                                 \
        QV = -3.0e38f; QJ = (Q) * 8;                                  \
        _Pragma("unroll")                                             \
        for (int j0 = 0; j0 < 8; j0++) {                              \
            int j = (Q) * 8 + j0;                                     \
            float v = ((alive >> j) & 1u) ? vals[j] : -3.0e38f;       \
            if (v > QV) { QV = v; QJ = j; }                           \
        }                                                             \
    }

    RESCANQ(0, qv0, qj0)
    RESCANQ(1, qv1, qj1)
    RESCANQ(2, qv2, qj2)
    RESCANQ(3, qv3, qj3)

    float lv = qv0; int li = qj0;
    if (qv1 > lv) { lv = qv1; li = qj1; }
    if (qv2 > lv) { lv = qv2; li = qj2; }
    if (qv3 > lv) { lv = qv3; li = qj3; }

    int myout = 0;
    for (int k = 0; k < KK; k++) {
        float bv = lv;
        int bi = li * 32 + lane;
#pragma unroll
        for (int s = 16; s; s >>= 1) {
            float ov = __shfl_xor_sync(0xffffffffu, bv, s);
            int oi = __shfl_xor_sync(0xffffffffu, bi, s);
            if (ov > bv || (ov == bv && oi < bi)) { bv = ov; bi = oi; }
        }
        if (lane == k) myout = bi;
        if (lane == (bi & 31)) {
            int jrem = bi >> 5;
            alive &= ~(1u << jrem);
            int q = jrem >> 3;
            if (q == 0)      RESCANQ(0, qv0, qj0)
            else if (q == 1) RESCANQ(1, qv1, qj1)
            else if (q == 2) RESCANQ(2, qv2, qj2)
            else             RESCANQ(3, qv3, qj3)
            lv = qv0; li = qj0;
            if (qv1 > lv) { lv = qv1; li = qj1; }
            if (qv2 > lv) { lv = qv2; li = qj2; }
            if (qv3 > lv) { lv = qv3; li = qj3; }
        }
    }
    if (lane < KK) g_idx[rowg * KK + lane] = myout;
#undef RESCANQ
}

// -------- v = Wa@x, u = (Wb-Wa)@x ; block = O threads, 16 points/block --------
__global__ void k2_kernel(int src, int off, int stride, int C, int O) {
    __shared__ float sf[16 * 128];
    int b = blockIdx.y;
    int n0 = blockIdx.x * 16;
    int o = threadIdx.x;
    const float* fb = featPtr(src, off) + ((size_t)b * NN + n0) * stride;
    for (int l = o; l < 16 * C; l += O) {
        int p = l / C, c = l % C;
        sf[p * C + c] = fb[(size_t)p * stride + c];
    }
    __syncthreads();
    float va[16], vu[16];
#pragma unroll
    for (int p = 0; p < 16; p++) { va[p] = 0.f; vu[p] = 0.f; }
    for (int c = 0; c < C; c++) {
        float wa = g_wa[c * O + o];
        float wu = g_wu[c * O + o];
#pragma unroll
        for (int p = 0; p < 16; p++) {
            float f = sf[p * C + c];
            va[p] = fmaf(wa, f, va[p]);
            vu[p] = fmaf(wu, f, vu[p]);
        }
    }
#pragma unroll
    for (int p = 0; p < 16; p++) {
        size_t idx = ((size_t)b * NN + n0 + p) * O + o;
        g_v[idx] = va[p];
        g_u[idx] = vu[p];
    }
}

// -------- gather + k-reduce + channel stats --------
__global__ void k3_kernel(int O) {
    int b = blockIdx.y;
    int n0 = blockIdx.x * 16;
    int o = threadIdx.x;
    size_t base = (size_t)b * NN;
    float s = 0.f, q = 0.f;
    for (int p = 0; p < 16; p++) {
        int n = n0 + p;
        const int* id = g_idx + (base + n) * KK;
        float uu = g_u[(base + n) * O + o];
        float mx = -3.0e38f, mn = 3.0e38f;
#pragma unroll
        for (int k = 0; k < KK; k++) {
            int j = id[k];
            float y = g_v[(base + j) * O + o] + uu;
            mx = fmaxf(mx, y);
            mn = fminf(mn, y);
            s += y;
            q = fmaf(y, y, q);
        }
        g_maxv[(base + n) * O + o] = mx;
        g_minv[(base + n) * O + o] = mn;
    }
    atomicAdd(&g_sum[o], s);
    atomicAdd(&g_sq[o], q);
}

// -------- BN finalize per channel --------
__global__ void k4a(const float* __restrict__ gam, const float* __restrict__ bet,
                    float cnt, int O) {
    int o = threadIdx.x;
    if (o >= O) return;
    float m = g_sum[o] / cnt;
    float var = g_sq[o] / cnt - m * m;
    float sc = gam[o] * rsqrtf(var + 1e-5f);
    g_scale[o] = sc;
    g_bias[o] = bet[o] - m * sc;
}

// -------- apply BN + lrelu on the k-pooled value, write into cat; zero f1 stats --------
__global__ void k4b(int O, int coff) {
    if (blockIdx.x == 0) {
        for (int t = threadIdx.x; t < O5; t += 256) { g_sum[t] = 0.f; g_sq[t] = 0.f; }
    }
    int t = blockIdx.x * blockDim.x + threadIdx.x;
    if (t >= BB * NN * O) return;
    int o = t % O;
    size_t pn = t / O;
    float sc = g_scale[o], bi = g_bias[o];
    float sel = (sc >= 0.f) ? g_maxv[t] : g_minv[t];
    float y = fmaf(sc, sel, bi);
    g_cat[pn * CAT + coff + o] = (y >= 0.f) ? y : 0.2f * y;
}

// -------- final conv1d GEMM: 128x128 tile, 8x8 micro, f32x2, fused n-stats --------
__global__ __launch_bounds__(256, 2) void f1_kernel(const float* __restrict__ W5) {
    __shared__ float Ad[16 * 258];
    __shared__ float Bs_[16 * 132];
    int ob = blockIdx.x * 128;
    int nb = blockIdx.y * 128;
    int b = blockIdx.z;
    int tid = threadIdx.x;
    int tx = tid & 15, ty = tid >> 4;
    const float* cb = g_cat + (size_t)b * NN * CAT;

    ull acc[8][4];
#pragma unroll
    for (int i = 0; i < 8; i++)
#pragma unroll
        for (int j = 0; j < 4; j++) acc[i][j] = 0ull;

    for (int cc = 0; cc < 32; cc++) {
#pragma unroll
        for (int l0 = 0; l0 < 8; l0++) {
            int l = l0 * 256 + tid;
            int c = l & 15, r = l >> 4;
            float a = W5[(size_t)(ob + r) * 512 + (cc << 4) + c];
            float bv = cb[(size_t)(nb + r) * 512 + (cc << 4) + c];
            *(ull*)&Ad[c * 258 + 2 * r] = bcast2(a);
            Bs_[c * 132 + r] = bv;
        }
        __syncthreads();
#pragma unroll
        for (int c = 0; c < 16; c++) {
            const float* arow = &Ad[c * 258 + ty * 16];
            const float* brow = &Bs_[c * 132 + tx * 8];
            ull b0 = *(const ull*)&brow[0];
            ull b1 = *(const ull*)&brow[2];
            ull b2 = *(const ull*)&brow[4];
            ull b3 = *(const ull*)&brow[6];
#pragma unroll
            for (int i = 0; i < 8; i++) {
                ull ap = *(const ull*)&arow[2 * i];
                acc[i][0] = ffma2(ap, b0, acc[i][0]);
                acc[i][1] = ffma2(ap, b1, acc[i][1]);
                acc[i][2] = ffma2(ap, b2, acc[i][2]);
                acc[i][3] = ffma2(ap, b3, acc[i][3]);
            }
        }
        __syncthreads();
    }

    // epilogue: per-o stats over this 128-n tile
#pragma unroll
    for (int i = 0; i < 8; i++) {
        float v[8];
#pragma unroll
        for (int j = 0; j < 4; j++) unpack2(acc[i][j], v[2 * j], v[2 * j + 1]);
        float mx = v[0], mn = v[0], s = v[0], q = v[0] * v[0];
#pragma unroll
        for (int j = 1; j < 8; j++) {
            mx = fmaxf(mx, v[j]);
            mn = fminf(mn, v[j]);
            s += v[j];
            q = fmaf(v[j], v[j], q);
        }
#pragma unroll
        for (int st = 8; st; st >>= 1) {
            mx = fmaxf(mx, __shfl_xor_sync(0xffffffffu, mx, st));
            mn = fminf(mn, __shfl_xor_sync(0xffffffffu, mn, st));
            s += __shfl_xor_sync(0xffffffffu, s, st);
            q += __shfl_xor_sync(0xffffffffu, q, st);
        }
        if (tx == 0) {
            int o = ob + ty * 8 + i;
            g_pmax[((size_t)b * O5 + o) * 8 + blockIdx.y] = mx;
            g_pmin[((size_t)b * O5 + o) * 8 + blockIdx.y] = mn;
            atomicAdd(&g_sum[o], s);
            atomicAdd(&g_sq[o], q);
        }
    }
}

// -------- final BN + lrelu + max over n --------
__global__ void f2_kernel(const float* __restrict__ g5, const float* __restrict__ b5,
                          float* __restrict__ out) {
    int t = blockIdx.x * blockDim.x + threadIdx.x;
    if (t >= BB * O5) return;
    int b = t / O5, o = t % O5;
    float m = g_sum[o] / 8192.f;
    float var = g_sq[o] / 8192.f - m * m;
    float sc = g5[o] * rsqrtf(var + 1e-5f);
    float bi = b5[o] - m * sc;
    size_t base = ((size_t)b * O5 + o) * 8;
    float sel;
    if (sc >= 0.f) {
        sel = g_pmax[base];
        for (int i = 1; i < 8; i++) sel = fmaxf(sel, g_pmax[base + i]);
    } else {
        sel = g_pmin[base];
        for (int i = 1; i < 8; i++) sel = fminf(sel, g_pmin[base + i]);
    }
    float y = fmaf(sc, sel, bi);
    out[t] = (y >= 0.f) ? y : 0.2f * y;
}

extern "C" void kernel_launch(void* const* d_in, const int* in_sizes, int n_in,
                              void* d_out, int out_size) {
    const float* x  = (const float*)d_in[0];
    const float* Wl[4] = {(const float*)d_in[1], (const float*)d_in[4],
                          (const float*)d_in[7], (const float*)d_in[10]};
    const float* gl[4] = {(const float*)d_in[2], (const float*)d_in[5],
                          (const float*)d_in[8], (const float*)d_in[11]};
    const float* bl[4] = {(const float*)d_in[3], (const float*)d_in[6],
                          (const float*)d_in[9], (const float*)d_in[12]};
    const float* W5 = (const float*)d_in[13];
    const float* g5 = (const float*)d_in[14];
    const float* b5 = (const float*)d_in[15];
    float* out = (float*)d_out;

    prep0<<<32, 256>>>(x);

    const int srcA[4]  = {0, 1, 1, 1};
    const int offA[4]  = {0, 0, 64, 128};
    const int CA[4]    = {3, 64, 64, 128};
    const int OA[4]    = {64, 64, 128, 256};
    const int coffA[4] = {0, 64, 128, 256};

    for (int L = 0; L < 4; L++) {
        int src = srcA[L], off = offA[L], C = CA[L], O = OA[L], coff = coffA[L];
        int stride = src ? CAT : 4;
        prep_layer<<<161, 256>>>(Wl[L], src, off, stride, C, O);
        kd_kernel<<<dim3(8, 8, BB), 256>>>(src, off, stride, C);
        topk_kernel<<<BB * NN / 8, 256>>>();
        k2_kernel<<<dim3(NN / 16, BB), O>>>(src, off, stride, C, O);
        k3_kernel<<<dim3(NN / 16, BB), O>>>(O);
        k4a<<<1, O>>>(gl[L], bl[L], (float)(BB * NN * KK), O);
        k4b<<<(BB * NN * O + 255) / 256, 256>>>(O, coff);
    }

    f1_kernel<<<dim3(8, 8, BB), 256>>>(W5);
    f2_kernel<<<32, 256>>>(g5, b5, out);
}

// round 5
// speedup vs baseline: 1.9050x; 1.1627x over previous
#include <cuda_runtime.h>

#define BB 8
#define NN 1024
#define KK 20
#define CAT 512
#define O5 1024

typedef unsigned long long ull;

__device__ __forceinline__ ull ffma2(ull a, ull b, ull c) {
    ull d;
    asm("fma.rn.f32x2 %0, %1, %2, %3;" : "=l"(d) : "l"(a), "l"(b), "l"(c));
    return d;
}
__device__ __forceinline__ ull bcast2(float v) {
    ull d;
    asm("mov.b64 %0, {%1, %1};" : "=l"(d) : "f"(v));
    return d;
}
__device__ __forceinline__ void unpack2(ull p, float& lo, float& hi) {
    asm("mov.b64 {%0, %1}, %2;" : "=f"(lo), "=f"(hi) : "l"(p));
}

// -------- static device workspaces --------
__device__ float g_f0[BB * NN * 4];
__device__ float g_cat[BB * NN * CAT];
__device__ float g_xx[BB * NN];
__device__ float g_nd[BB * NN * NN];
__device__ int   g_idx[BB * NN * KK];
__device__ float g_v[BB * NN * 256];
__device__ float g_u[BB * NN * 256];
__device__ float g_wa[64 * 1024];
__device__ float g_wu[64 * 1024];
__device__ float g_maxv[BB * NN * 256];
__device__ float g_minv[BB * NN * 256];
__device__ float g_sum[O5];
__device__ float g_sq[O5];
__device__ float g_pmax[BB * O5 * 8];
__device__ float g_pmin[BB * O5 * 8];
__device__ float g_scale[256];
__device__ float g_bias[256];
__device__ int   g_cnt;

__device__ __forceinline__ const float* featPtr(int src, int off) {
    return src ? (g_cat + off) : g_f0;
}

// -------- fused prep: transpose x + xx(layer1) + ALL W splits + zero stats --------
__global__ void prep0(const float* __restrict__ x,
                      const float* __restrict__ W1, const float* __restrict__ W2,
                      const float* __restrict__ W3, const float* __restrict__ W4) {
    int bx = blockIdx.x;
    if (bx < 32) {
        int t = bx * 256 + threadIdx.x;
        int b = t / NN, n = t % NN;
        float x0 = x[(b * 3 + 0) * NN + n];
        float x1 = x[(b * 3 + 1) * NN + n];
        float x2 = x[(b * 3 + 2) * NN + n];
        float* d = g_f0 + (size_t)t * 4;
        d[0] = x0; d[1] = x1; d[2] = x2; d[3] = 0.f;
        float a = fmaf(x0, x0, 0.f);
        a = fmaf(x1, x1, a);
        a = fmaf(x2, x2, a);
        g_xx[t] = a;
    } else if (bx == 32) {
        for (int t = threadIdx.x; t < O5; t += 256) { g_sum[t] = 0.f; g_sq[t] = 0.f; }
    } else {
        int t = (bx - 33) * 256 + threadIdx.x;
        const float* W; int C, O, woff, local;
        if (t < 192)        { W = W1; C = 3;   O = 64;  woff = 0;     local = t; }
        else if (t < 4288)  { W = W2; C = 64;  O = 64;  woff = 256;   local = t - 192; }
        else if (t < 12480) { W = W3; C = 64;  O = 128; woff = 4608;  local = t - 4288; }
        else if (t < 45248) { W = W4; C = 128; O = 256; woff = 12800; local = t - 12480; }
        else return;
        int c = local / O, o = local % O;
        float wa = W[o * (2 * C) + c];
        float wb = W[o * (2 * C) + C + c];
        g_wa[woff + c * O + o] = wa;
        g_wu[woff + c * O + o] = wb - wa;
    }
}

// -------- neg pairwise distance Gram GEMM: symmetric, 128x128 tile, 8x8, f32x2 --------
__global__ __launch_bounds__(256, 2) void kd_kernel(int src, int off, int stride, int C) {
    __shared__ float Ad[16 * 258];
    __shared__ float Bs_[16 * 132];
    int b = blockIdx.z;
    // map blockIdx.x in [0,36) to upper-triangular (bi<=bj) of 8x8 block grid
    int bi = 0, rem = blockIdx.x;
    while (rem >= 8 - bi) { rem -= 8 - bi; bi++; }
    int bj = bi + rem;
    int ib = bi * 128, jb = bj * 128;
    int tid = threadIdx.x;
    int tx = tid & 15, ty = tid >> 4;
    const float* fb = featPtr(src, off) + (size_t)b * NN * stride;

    ull acc[8][4];
#pragma unroll
    for (int i = 0; i < 8; i++)
#pragma unroll
        for (int j = 0; j < 4; j++) acc[i][j] = 0ull;

    int nch = (C + 15) >> 4;
    for (int cc = 0; cc < nch; cc++) {
#pragma unroll
        for (int l0 = 0; l0 < 8; l0++) {
            int l = l0 * 256 + tid;
            int c = l & 15, r = l >> 4;
            int cg = (cc << 4) + c;
            float a = 0.f, bv = 0.f;
            if (cg < C) {
                a = fb[(size_t)(ib + r) * stride + cg];
                bv = fb[(size_t)(jb + r) * stride + cg];
            }
            *(ull*)&Ad[c * 258 + 2 * r] = bcast2(a);
            Bs_[c * 132 + r] = bv;
        }
        __syncthreads();
#pragma unroll
        for (int c = 0; c < 16; c++) {
            const float* arow = &Ad[c * 258 + ty * 16];
            const float* brow = &Bs_[c * 132 + tx * 8];
            ull b0 = *(const ull*)&brow[0];
            ull b1 = *(const ull*)&brow[2];
            ull b2 = *(const ull*)&brow[4];
            ull b3 = *(const ull*)&brow[6];
#pragma unroll
            for (int i = 0; i < 8; i++) {
                ull ap = *(const ull*)&arow[2 * i];
                acc[i][0] = ffma2(ap, b0, acc[i][0]);
                acc[i][1] = ffma2(ap, b1, acc[i][1]);
                acc[i][2] = ffma2(ap, b2, acc[i][2]);
                acc[i][3] = ffma2(ap, b3, acc[i][3]);
            }
        }
        __syncthreads();
    }

    const float* xxb = g_xx + b * NN;
    float xm[8], xn[8];
#pragma unroll
    for (int j = 0; j < 8; j++) xm[j] = xxb[jb + tx * 8 + j];
#pragma unroll
    for (int i = 0; i < 8; i++) xn[i] = xxb[ib + ty * 8 + i];
    float* nd = g_nd + (size_t)b * NN * NN;

#pragma unroll
    for (int i = 0; i < 8; i++) {
        float v[8];
#pragma unroll
        for (int j = 0; j < 4; j++) unpack2(acc[i][j], v[2 * j], v[2 * j + 1]);
        float4 o0, o1;
        o0.x = 2.f * v[0] - xn[i] - xm[0];
        o0.y = 2.f * v[1] - xn[i] - xm[1];
        o0.z = 2.f * v[2] - xn[i] - xm[2];
        o0.w = 2.f * v[3] - xn[i] - xm[3];
        o1.x = 2.f * v[4] - xn[i] - xm[4];
        o1.y = 2.f * v[5] - xn[i] - xm[5];
        o1.z = 2.f * v[6] - xn[i] - xm[6];
        o1.w = 2.f * v[7] - xn[i] - xm[7];
        float4* dst = (float4*)(nd + (size_t)(ib + ty * 8 + i) * NN + jb + tx * 8);
        dst[0] = o0;
        dst[1] = o1;
    }
    if (bi != bj) {   // mirror into the lower-triangular block (same values)
#pragma unroll
        for (int j = 0; j < 8; j++) {
            float tmp[8];
#pragma unroll
            for (int i = 0; i < 8; i++) {
                float lo, hi;
                unpack2(acc[i][j >> 1], lo, hi);
                float mv = (j & 1) ? hi : lo;
                tmp[i] = 2.f * mv - xn[i] - xm[j];
            }
            float4* d2 = (float4*)(nd + (size_t)(jb + tx * 8 + j) * NN + ib + ty * 8);
            d2[0] = make_float4(tmp[0], tmp[1], tmp[2], tmp[3]);
            d2[1] = make_float4(tmp[4], tmp[5], tmp[6], tmp[7]);
        }
    }
}

__device__ __forceinline__ ull packkey(float v, int gidx) {
    unsigned bb = __float_as_uint(v);
    bb ^= (unsigned)(((int)bb >> 31)) | 0x80000000u;
    return ((ull)bb << 32) | (ull)(1023 - gidx);
}

// -------- fused: top-20 (blocks 0..1023) + v/u GEMM (rest) --------
__global__ __launch_bounds__(256, 4) void tk2_kernel(int src, int off, int stride,
                                                     int C, int O, int och, int woff) {
    __shared__ float sf[16 * 128];
    if (blockIdx.x < 1024) {
        // ---- topk: one warp per row, quartered cache, packed-u64 reduce ----
        int wid = threadIdx.x >> 5;
        int lane = threadIdx.x & 31;
        int rowg = blockIdx.x * 8 + wid;
        const float* row = g_nd + (size_t)rowg * NN;

        float vals[32];
#pragma unroll
        for (int j = 0; j < 32; j++) vals[j] = row[j * 32 + lane];

        unsigned alive = 0xffffffffu;
        float qv0, qv1, qv2, qv3;
        int qj0, qj1, qj2, qj3;

#define RESCANQ(Q, QV, QJ)                                            \
        {                                                             \
            QV = -3.0e38f; QJ = (Q) * 8;                              \
            _Pragma("unroll")                                         \
            for (int j0 = 0; j0 < 8; j0++) {                          \
                int j = (Q) * 8 + j0;                                 \
                float v = ((alive >> j) & 1u) ? vals[j] : -3.0e38f;   \
                if (v > QV) { QV = v; QJ = j; }                       \
            }                                                         \
        }

        RESCANQ(0, qv0, qj0)
        RESCANQ(1, qv1, qj1)
        RESCANQ(2, qv2, qj2)
        RESCANQ(3, qv3, qj3)

        float lv = qv0; int li = qj0;
        if (qv1 > lv) { lv = qv1; li = qj1; }
        if (qv2 > lv) { lv = qv2; li = qj2; }
        if (qv3 > lv) { lv = qv3; li = qj3; }

        int myout = 0;
        for (int k = 0; k < KK; k++) {
            ull key = packkey(lv, li * 32 + lane);
#pragma unroll
            for (int s = 16; s; s >>= 1) {
                ull ok = __shfl_xor_sync(0xffffffffu, key, s);
                key = (ok > key) ? ok : key;
            }
            int gidx = 1023 - (int)(key & 0xffffffffu);
            if (lane == k) myout = gidx;
            if (lane == (gidx & 31)) {
                int jrem = gidx >> 5;
                alive &= ~(1u << jrem);
                int q = jrem >> 3;
                if (q == 0)      RESCANQ(0, qv0, qj0)
                else if (q == 1) RESCANQ(1, qv1, qj1)
                else if (q == 2) RESCANQ(2, qv2, qj2)
                else             RESCANQ(3, qv3, qj3)
                lv = qv0; li = qj0;
                if (qv1 > lv) { lv = qv1; li = qj1; }
                if (qv2 > lv) { lv = qv2; li = qj2; }
                if (qv3 > lv) { lv = qv3; li = qj3; }
            }
        }
        if (lane < KK) g_idx[rowg * KK + lane] = myout;
#undef RESCANQ
    } else {
        // ---- k2: v = Wa@x, u = (Wb-Wa)@x ; 64 o-channels x 16 points / block ----
        int kb = blockIdx.x - 1024;
        int bpb = 64 * och;
        int b = kb / bpb;
        int rm = kb % bpb;
        int n0 = (rm / och) * 16;
        int o0 = (rm % och) * 64;
        int og = threadIdx.x & 63;
        int pg = threadIdx.x >> 6;           // 0..3, 4 points each
        int o = o0 + og;
        const float* fb = featPtr(src, off) + ((size_t)b * NN + n0) * stride;
        for (int l = threadIdx.x; l < 16 * C; l += 256) {
            int p = l / C, c = l % C;
            sf[p * C + c] = fb[(size_t)p * stride + c];
        }
        __syncthreads();
        float va[4], vu[4];
#pragma unroll
        for (int p = 0; p < 4; p++) { va[p] = 0.f; vu[p] = 0.f; }
        const float* wap = g_wa + woff + o;
        const float* wup = g_wu + woff + o;
        const float* sfp = sf + pg * 4 * C;
        for (int c = 0; c < C; c++) {
            float wa = wap[c * O];
            float wu = wup[c * O];
#pragma unroll
            for (int p = 0; p < 4; p++) {
                float f = sfp[p * C + c];
                va[p] = fmaf(wa, f, va[p]);
                vu[p] = fmaf(wu, f, vu[p]);
            }
        }
#pragma unroll
        for (int p = 0; p < 4; p++) {
            size_t idx = ((size_t)b * NN + n0 + pg * 4 + p) * O + o;
            g_v[idx] = va[p];
            g_u[idx] = vu[p];
        }
    }
}

// -------- gather + k-reduce + channel stats + folded BN finalize --------
__global__ void k3_kernel(const float* __restrict__ gam, const float* __restrict__ bet,
                          int O, int total_blocks) {
    int b = blockIdx.y;
    int n0 = blockIdx.x * 16;
    int o = threadIdx.x;
    size_t base = (size_t)b * NN;
    float s = 0.f, q = 0.f;
    for (int p = 0; p < 16; p++) {
        int n = n0 + p;
        const int* id = g_idx + (base + n) * KK;
        float uu = g_u[(base + n) * O + o];
        float mx = -3.0e38f, mn = 3.0e38f;
#pragma unroll
        for (int k = 0; k < KK; k++) {
            int j = id[k];
            float y = g_v[(base + j) * O + o] + uu;
            mx = fmaxf(mx, y);
            mn = fminf(mn, y);
            s += y;
            q = fmaf(y, y, q);
        }
        g_maxv[(base + n) * O + o] = mx;
        g_minv[(base + n) * O + o] = mn;
    }
    atomicAdd(&g_sum[o], s);
    atomicAdd(&g_sq[o], q);

    // last-block: BN finalize (replaces k4a launch)
    __threadfence();
    __shared__ int isLast;
    if (threadIdx.x == 0) isLast = (atomicAdd(&g_cnt, 1) == total_blocks - 1);
    __syncthreads();
    if (isLast) {
        volatile float* vs = g_sum;
        volatile float* vq = g_sq;
        float cnt = (float)(BB * NN * KK);
        float m = vs[o] / cnt;
        float var = vq[o] / cnt - m * m;
        float sc = gam[o] * rsqrtf(var + 1e-5f);
        g_scale[o] = sc;
        g_bias[o] = bet[o] - m * sc;
        if (o == 0) g_cnt = 0;
    }
}

// -------- BN+lrelu apply -> cat ; fused next-layer xx ; zero stats --------
__global__ void k4b(int O, int coff, int do_xx) {
    __shared__ float sq_s[8];
    if (blockIdx.x == 0) {
        for (int z = threadIdx.x; z < O5; z += 256) { g_sum[z] = 0.f; g_sq[z] = 0.f; }
    }
    int t = blockIdx.x * 256 + threadIdx.x;
    int o = t % O;
    size_t pn = t / O;
    float sc = g_scale[o], bi = g_bias[o];
    float sel = (sc >= 0.f) ? g_maxv[t] : g_minv[t];
    float y = fmaf(sc, sel, bi);
    float act = (y >= 0.f) ? y : 0.2f * y;
    g_cat[pn * CAT + coff + o] = act;
    if (do_xx) {
        float q = act * act;
#pragma unroll
        for (int s = 16; s; s >>= 1) q += __shfl_xor_sync(0xffffffffu, q, s);
        if ((threadIdx.x & 31) == 0) sq_s[threadIdx.x >> 5] = q;
        __syncthreads();
        int pts = 256 / O, wpp = O / 32;
        if (threadIdx.x < pts) {
            float a = 0.f;
            for (int w = 0; w < wpp; w++) a += sq_s[threadIdx.x * wpp + w];
            g_xx[(size_t)blockIdx.x * pts + threadIdx.x] = a;
        }
    }
}

// -------- final conv1d GEMM: 128x128 tile, 8x8 micro, f32x2, fused n-stats --------
__global__ __launch_bounds__(256, 2) void f1_kernel(const float* __restrict__ W5) {
    __shared__ float Ad[16 * 258];
    __shared__ float Bs_[16 * 132];
    int ob = blockIdx.x * 128;
    int nb = blockIdx.y * 128;
    int b = blockIdx.z;
    int tid = threadIdx.x;
    int tx = tid & 15, ty = tid >> 4;
    const float* cb = g_cat + (size_t)b * NN * CAT;

    ull acc[8][4];
#pragma unroll
    for (int i = 0; i < 8; i++)
#pragma unroll
        for (int j = 0; j < 4; j++) acc[i][j] = 0ull;

    for (int cc = 0; cc < 32; cc++) {
#pragma unroll
        for (int l0 = 0; l0 < 8; l0++) {
            int l = l0 * 256 + tid;
            int c = l & 15, r = l >> 4;
            float a = W5[(size_t)(ob + r) * 512 + (cc << 4) + c];
            float bv = cb[(size_t)(nb + r) * 512 + (cc << 4) + c];
            *(ull*)&Ad[c * 258 + 2 * r] = bcast2(a);
            Bs_[c * 132 + r] = bv;
        }
        __syncthreads();
#pragma unroll
        for (int c = 0; c < 16; c++) {
            const float* arow = &Ad[c * 258 + ty * 16];
            const float* brow = &Bs_[c * 132 + tx * 8];
            ull b0 = *(const ull*)&brow[0];
            ull b1 = *(const ull*)&brow[2];
            ull b2 = *(const ull*)&brow[4];
            ull b3 = *(const ull*)&brow[6];
#pragma unroll
            for (int i = 0; i < 8; i++) {
                ull ap = *(const ull*)&arow[2 * i];
                acc[i][0] = ffma2(ap, b0, acc[i][0]);
                acc[i][1] = ffma2(ap, b1, acc[i][1]);
                acc[i][2] = ffma2(ap, b2, acc[i][2]);
                acc[i][3] = ffma2(ap, b3, acc[i][3]);
            }
        }
        __syncthreads();
    }

#pragma unroll
    for (int i = 0; i < 8; i++) {
        float v[8];
#pragma unroll
        for (int j = 0; j < 4; j++) unpack2(acc[i][j], v[2 * j], v[2 * j + 1]);
        float mx = v[0], mn = v[0], s = v[0], q = v[0] * v[0];
#pragma unroll
        for (int j = 1; j < 8; j++) {
            mx = fmaxf(mx, v[j]);
            mn = fminf(mn, v[j]);
            s += v[j];
            q = fmaf(v[j], v[j], q);
        }
#pragma unroll
        for (int st = 8; st; st >>= 1) {
            mx = fmaxf(mx, __shfl_xor_sync(0xffffffffu, mx, st));
            mn = fminf(mn, __shfl_xor_sync(0xffffffffu, mn, st));
            s += __shfl_xor_sync(0xffffffffu, s, st);
            q += __shfl_xor_sync(0xffffffffu, q, st);
        }
        if (tx == 0) {
            int o = ob + ty * 8 + i;
            g_pmax[((size_t)b * O5 + o) * 8 + blockIdx.y] = mx;
            g_pmin[((size_t)b * O5 + o) * 8 + blockIdx.y] = mn;
            atomicAdd(&g_sum[o], s);
            atomicAdd(&g_sq[o], q);
        }
    }
}

// -------- final BN + lrelu + max over n --------
__global__ void f2_kernel(const float* __restrict__ g5, const float* __restrict__ b5,
                          float* __restrict__ out) {
    int t = blockIdx.x * blockDim.x + threadIdx.x;
    if (t >= BB * O5) return;
    int b = t / O5, o = t % O5;
    float m = g_sum[o] / 8192.f;
    float var = g_sq[o] / 8192.f - m * m;
    float sc = g5[o] * rsqrtf(var + 1e-5f);
    float bi = b5[o] - m * sc;
    size_t base = ((size_t)b * O5 + o) * 8;
    float sel;
    if (sc >= 0.f) {
        sel = g_pmax[base];
        for (int i = 1; i < 8; i++) sel = fmaxf(sel, g_pmax[base + i]);
    } else {
        sel = g_pmin[base];
        for (int i = 1; i < 8; i++) sel = fminf(sel, g_pmin[base + i]);
    }
    float y = fmaf(sc, sel, bi);
    out[t] = (y >= 0.f) ? y : 0.2f * y;
}

extern "C" void kernel_launch(void* const* d_in, const int* in_sizes, int n_in,
                              void* d_out, int out_size) {
    const float* x  = (const float*)d_in[0];
    const float* Wl[4] = {(const float*)d_in[1], (const float*)d_in[4],
                          (const float*)d_in[7], (const float*)d_in[10]};
    const float* gl[4] = {(const float*)d_in[2], (const float*)d_in[5],
                          (const float*)d_in[8], (const float*)d_in[11]};
    const float* bl[4] = {(const float*)d_in[3], (const float*)d_in[6],
                          (const float*)d_in[9], (const float*)d_in[12]};
    const float* W5 = (const float*)d_in[13];
    const float* g5 = (const float*)d_in[14];
    const float* b5 = (const float*)d_in[15];
    float* out = (float*)d_out;

    prep0<<<210, 256>>>(x, Wl[0], Wl[1], Wl[2], Wl[3]);

    const int srcA[4]  = {0, 1, 1, 1};
    const int offA[4]  = {0, 0, 64, 128};
    const int CA[4]    = {3, 64, 64, 128};
    const int OA[4]    = {64, 64, 128, 256};
    const int coffA[4] = {0, 64, 128, 256};
    const int woffA[4] = {0, 256, 4608, 12800};

    for (int L = 0; L < 4; L++) {
        int src = srcA[L], off = offA[L], C = CA[L], O = OA[L], coff = coffA[L];
        int woff = woffA[L];
        int stride = src ? CAT : 4;
        int och = O / 64;
        kd_kernel<<<dim3(36, 1, BB), 256>>>(src, off, stride, C);
        tk2_kernel<<<1024 + 512 * och, 256>>>(src, off, stride, C, O, och, woff);
        k3_kernel<<<dim3(64, BB), O>>>(gl[L], bl[L], O, 512);
        k4b<<<BB * NN * O / 256, 256>>>(O, coff, (L < 3) ? 1 : 0);
    }

    f1_kernel<<<dim3(8, 8, BB), 256>>>(W5);
    f2_kernel<<<32, 256>>>(g5, b5, out);
}

// round 6
// speedup vs baseline: 1.9291x; 1.0127x over previous
#include <cuda_runtime.h>

#define BB 8
#define NN 1024
#define KK 20
#define CAT 512
#define O5 1024

typedef unsigned long long ull;

__device__ __forceinline__ ull ffma2(ull a, ull b, ull c) {
    ull d;
    asm("fma.rn.f32x2 %0, %1, %2, %3;" : "=l"(d) : "l"(a), "l"(b), "l"(c));
    return d;
}
__device__ __forceinline__ ull bcast2(float v) {
    ull d;
    asm("mov.b64 %0, {%1, %1};" : "=l"(d) : "f"(v));
    return d;
}
__device__ __forceinline__ void unpack2(ull p, float& lo, float& hi) {
    asm("mov.b64 {%0, %1}, %2;" : "=f"(lo), "=f"(hi) : "l"(p));
}

// -------- static device workspaces --------
__device__ float g_f0[BB * NN * 4];
__device__ float g_cat[BB * NN * CAT];
__device__ float g_xx[BB * NN];
__device__ float g_nd[BB * NN * NN];
__device__ int   g_idx[BB * NN * KK];
__device__ float g_v[BB * NN * 256];
__device__ float g_u[BB * NN * 256];
__device__ float g_wa[64 * 1024];
__device__ float g_wu[64 * 1024];
__device__ float g_maxv[BB * NN * 256];
__device__ float g_minv[BB * NN * 256];
__device__ float g_sum[O5];
__device__ float g_sq[O5];
__device__ float g_pmax[BB * O5 * 8];
__device__ float g_pmin[BB * O5 * 8];
__device__ float g_scale[256];
__device__ float g_bias[256];
__device__ int   g_cnt;

__device__ __forceinline__ const float* featPtr(int src, int off) {
    return src ? (g_cat + off) : g_f0;
}

// -------- fused prep: transpose x + xx(layer1) + ALL W splits + zero stats --------
__global__ void prep0(const float* __restrict__ x,
                      const float* __restrict__ W1, const float* __restrict__ W2,
                      const float* __restrict__ W3, const float* __restrict__ W4) {
    int bx = blockIdx.x;
    if (bx < 32) {
        int t = bx * 256 + threadIdx.x;
        int b = t / NN, n = t % NN;
        float x0 = x[(b * 3 + 0) * NN + n];
        float x1 = x[(b * 3 + 1) * NN + n];
        float x2 = x[(b * 3 + 2) * NN + n];
        float* d = g_f0 + (size_t)t * 4;
        d[0] = x0; d[1] = x1; d[2] = x2; d[3] = 0.f;
        float a = fmaf(x0, x0, 0.f);
        a = fmaf(x1, x1, a);
        a = fmaf(x2, x2, a);
        g_xx[t] = a;
    } else if (bx == 32) {
        for (int t = threadIdx.x; t < O5; t += 256) { g_sum[t] = 0.f; g_sq[t] = 0.f; }
    } else {
        int t = (bx - 33) * 256 + threadIdx.x;
        const float* W; int C, O, woff, local;
        if (t < 192)        { W = W1; C = 3;   O = 64;  woff = 0;     local = t; }
        else if (t < 4288)  { W = W2; C = 64;  O = 64;  woff = 256;   local = t - 192; }
        else if (t < 12480) { W = W3; C = 64;  O = 128; woff = 4608;  local = t - 4288; }
        else if (t < 45248) { W = W4; C = 128; O = 256; woff = 12800; local = t - 12480; }
        else return;
        int c = local / O, o = local % O;
        float wa = W[o * (2 * C) + c];
        float wb = W[o * (2 * C) + C + c];
        g_wa[woff + c * O + o] = wa;
        g_wu[woff + c * O + o] = wb - wa;
    }
}

// -------- neg pairwise distance Gram GEMM: symmetric, 128x128 tile, 8x8, f32x2 --------
__global__ __launch_bounds__(256, 2) void kd_kernel(int src, int off, int stride, int C) {
    __shared__ float Ad[16 * 258];
    __shared__ float Bs_[16 * 132];
    int b = blockIdx.z;
    int bi = 0, rem = blockIdx.x;
    while (rem >= 8 - bi) { rem -= 8 - bi; bi++; }
    int bj = bi + rem;
    int ib = bi * 128, jb = bj * 128;
    int tid = threadIdx.x;
    int tx = tid & 15, ty = tid >> 4;
    const float* fb = featPtr(src, off) + (size_t)b * NN * stride;

    ull acc[8][4];
#pragma unroll
    for (int i = 0; i < 8; i++)
#pragma unroll
        for (int j = 0; j < 4; j++) acc[i][j] = 0ull;

    int nch = (C + 15) >> 4;
    for (int cc = 0; cc < nch; cc++) {
#pragma unroll
        for (int l0 = 0; l0 < 8; l0++) {
            int l = l0 * 256 + tid;
            int c = l & 15, r = l >> 4;
            int cg = (cc << 4) + c;
            float a = 0.f, bv = 0.f;
            if (cg < C) {
                a = fb[(size_t)(ib + r) * stride + cg];
                bv = fb[(size_t)(jb + r) * stride + cg];
            }
            *(ull*)&Ad[c * 258 + 2 * r] = bcast2(a);
            Bs_[c * 132 + r] = bv;
        }
        __syncthreads();
#pragma unroll
        for (int c = 0; c < 16; c++) {
            const float* arow = &Ad[c * 258 + ty * 16];
            const float* brow = &Bs_[c * 132 + tx * 8];
            ull b0 = *(const ull*)&brow[0];
            ull b1 = *(const ull*)&brow[2];
            ull b2 = *(const ull*)&brow[4];
            ull b3 = *(const ull*)&brow[6];
#pragma unroll
            for (int i = 0; i < 8; i++) {
                ull ap = *(const ull*)&arow[2 * i];
                acc[i][0] = ffma2(ap, b0, acc[i][0]);
                acc[i][1] = ffma2(ap, b1, acc[i][1]);
                acc[i][2] = ffma2(ap, b2, acc[i][2]);
                acc[i][3] = ffma2(ap, b3, acc[i][3]);
            }
        }
        __syncthreads();
    }

    const float* xxb = g_xx + b * NN;
    float xm[8], xn[8];
#pragma unroll
    for (int j = 0; j < 8; j++) xm[j] = xxb[jb + tx * 8 + j];
#pragma unroll
    for (int i = 0; i < 8; i++) xn[i] = xxb[ib + ty * 8 + i];
    float* nd = g_nd + (size_t)b * NN * NN;

#pragma unroll
    for (int i = 0; i < 8; i++) {
        float v[8];
#pragma unroll
        for (int j = 0; j < 4; j++) unpack2(acc[i][j], v[2 * j], v[2 * j + 1]);
        float4 o0, o1;
        o0.x = 2.f * v[0] - xn[i] - xm[0];
        o0.y = 2.f * v[1] - xn[i] - xm[1];
        o0.z = 2.f * v[2] - xn[i] - xm[2];
        o0.w = 2.f * v[3] - xn[i] - xm[3];
        o1.x = 2.f * v[4] - xn[i] - xm[4];
        o1.y = 2.f * v[5] - xn[i] - xm[5];
        o1.z = 2.f * v[6] - xn[i] - xm[6];
        o1.w = 2.f * v[7] - xn[i] - xm[7];
        float4* dst = (float4*)(nd + (size_t)(ib + ty * 8 + i) * NN + jb + tx * 8);
        dst[0] = o0;
        dst[1] = o1;
    }
    if (bi != bj) {
#pragma unroll
        for (int j = 0; j < 8; j++) {
            float tmp[8];
#pragma unroll
            for (int i = 0; i < 8; i++) {
                float lo, hi;
                unpack2(acc[i][j >> 1], lo, hi);
                float mv = (j & 1) ? hi : lo;
                tmp[i] = 2.f * mv - xn[i] - xm[j];
            }
            float4* d2 = (float4*)(nd + (size_t)(jb + tx * 8 + j) * NN + ib + ty * 8);
            d2[0] = make_float4(tmp[0], tmp[1], tmp[2], tmp[3]);
            d2[1] = make_float4(tmp[4], tmp[5], tmp[6], tmp[7]);
        }
    }
}

__device__ __forceinline__ ull packkey(float v, int gidx) {
    unsigned bb = __float_as_uint(v);
    bb ^= (unsigned)(((int)bb >> 31)) | 0x80000000u;
    return ((ull)bb << 32) | (ull)(1023 - gidx);
}

// -------- fused: top-20 (blocks 0..1023) + v/u GEMM (rest) --------
__global__ __launch_bounds__(256, 4) void tk2_kernel(int src, int off, int stride,
                                                     int C, int O, int och, int woff) {
    __shared__ float sf[16 * 128];
    if (blockIdx.x < 1024) {
        int wid = threadIdx.x >> 5;
        int lane = threadIdx.x & 31;
        int rowg = blockIdx.x * 8 + wid;
        const float* row = g_nd + (size_t)rowg * NN;

        float vals[32];
#pragma unroll
        for (int j = 0; j < 32; j++) vals[j] = row[j * 32 + lane];

        unsigned alive = 0xffffffffu;
        float qv0, qv1, qv2, qv3;
        int qj0, qj1, qj2, qj3;

#define RESCANQ(Q, QV, QJ)                                            \
        {                                                             \
            QV = -3.0e38f; QJ = (Q) * 8;                              \
            _Pragma("unroll")                                         \
            for (int j0 = 0; j0 < 8; j0++) {                          \
                int j = (Q) * 8 + j0;                                 \
                float v = ((alive >> j) & 1u) ? vals[j] : -3.0e38f;   \
                if (v > QV) { QV = v; QJ = j; }                       \
            }                                                         \
        }

        RESCANQ(0, qv0, qj0)
        RESCANQ(1, qv1, qj1)
        RESCANQ(2, qv2, qj2)
        RESCANQ(3, qv3, qj3)

        float lv = qv0; int li = qj0;
        if (qv1 > lv) { lv = qv1; li = qj1; }
        if (qv2 > lv) { lv = qv2; li = qj2; }
        if (qv3 > lv) { lv = qv3; li = qj3; }

        int myout = 0;
        for (int k = 0; k < KK; k++) {
            ull key = packkey(lv, li * 32 + lane);
#pragma unroll
            for (int s = 16; s; s >>= 1) {
                ull ok = __shfl_xor_sync(0xffffffffu, key, s);
                key = (ok > key) ? ok : key;
            }
            int gidx = 1023 - (int)(key & 0xffffffffu);
            if (lane == k) myout = gidx;
            if (lane == (gidx & 31)) {
                int jrem = gidx >> 5;
                alive &= ~(1u << jrem);
                int q = jrem >> 3;
                if (q == 0)      RESCANQ(0, qv0, qj0)
                else if (q == 1) RESCANQ(1, qv1, qj1)
                else if (q == 2) RESCANQ(2, qv2, qj2)
                else             RESCANQ(3, qv3, qj3)
                lv = qv0; li = qj0;
                if (qv1 > lv) { lv = qv1; li = qj1; }
                if (qv2 > lv) { lv = qv2; li = qj2; }
                if (qv3 > lv) { lv = qv3; li = qj3; }
            }
        }
        if (lane < KK) g_idx[rowg * KK + lane] = myout;
#undef RESCANQ
    } else {
        int kb = blockIdx.x - 1024;
        int bpb = 64 * och;
        int b = kb / bpb;
        int rm = kb % bpb;
        int n0 = (rm / och) * 16;
        int o0 = (rm % och) * 64;
        int og = threadIdx.x & 63;
        int pg = threadIdx.x >> 6;
        int o = o0 + og;
        const float* fb = featPtr(src, off) + ((size_t)b * NN + n0) * stride;
        for (int l = threadIdx.x; l < 16 * C; l += 256) {
            int p = l / C, c = l % C;
            sf[p * C + c] = fb[(size_t)p * stride + c];
        }
        __syncthreads();
        float va[4], vu[4];
#pragma unroll
        for (int p = 0; p < 4; p++) { va[p] = 0.f; vu[p] = 0.f; }
        const float* wap = g_wa + woff + o;
        const float* wup = g_wu + woff + o;
        const float* sfp = sf + pg * 4 * C;
        for (int c = 0; c < C; c++) {
            float wa = wap[c * O];
            float wu = wup[c * O];
#pragma unroll
            for (int p = 0; p < 4; p++) {
                float f = sfp[p * C + c];
                va[p] = fmaf(wa, f, va[p]);
                vu[p] = fmaf(wu, f, vu[p]);
            }
        }
#pragma unroll
        for (int p = 0; p < 4; p++) {
            size_t idx = ((size_t)b * NN + n0 + pg * 4 + p) * O + o;
            g_v[idx] = va[p];
            g_u[idx] = vu[p];
        }
    }
}

// -------- gather + k-reduce + channel stats + folded BN finalize --------
// 256 threads: pp = tid/O point-lane (ppl = 256/O lanes), o = tid%O.
// Each lane handles 16/ppl points of the block's 16-point strip.
__global__ __launch_bounds__(256, 8) void k3_kernel(const float* __restrict__ gam,
                          const float* __restrict__ bet, int O, int total_blocks) {
    int b = blockIdx.y;
    int n0 = blockIdx.x * 16;
    int o = threadIdx.x % O;
    int pp = threadIdx.x / O;
    int ppl = 256 / O;
    int ppp = 16 / ppl;                  // points per lane
    size_t base = (size_t)b * NN;
    float s = 0.f, q = 0.f;
    for (int p = 0; p < ppp; p++) {
        int n = n0 + pp * ppp + p;
        const int* id = g_idx + (base + n) * KK;
        float uu = g_u[(base + n) * O + o];
        float mx = -3.0e38f, mn = 3.0e38f;
#pragma unroll
        for (int k = 0; k < KK; k++) {
            int j = id[k];
            float y = g_v[(base + j) * O + o] + uu;
            mx = fmaxf(mx, y);
            mn = fminf(mn, y);
            s += y;
            q = fmaf(y, y, q);
        }
        size_t t = (base + n) * O + o;
        g_maxv[t] = mx;
        g_minv[t] = mn;
    }
    atomicAdd(&g_sum[o], s);
    atomicAdd(&g_sq[o], q);

    __threadfence();
    __shared__ int isLast;
    if (threadIdx.x == 0) isLast = (atomicAdd(&g_cnt, 1) == total_blocks - 1);
    __syncthreads();
    if (isLast && threadIdx.x < O) {
        volatile float* vs = g_sum;
        volatile float* vq = g_sq;
        float cnt = (float)(BB * NN * KK);
        float m = vs[o] / cnt;
        float var = vq[o] / cnt - m * m;
        float sc = gam[o] * rsqrtf(var + 1e-5f);
        g_scale[o] = sc;
        g_bias[o] = bet[o] - m * sc;
        if (o == 0) g_cnt = 0;
    }
}

// -------- BN+lrelu apply -> cat ; fused next-layer xx ; zero stats --------
__global__ void k4b(int O, int coff, int do_xx) {
    __shared__ float sq_s[8];
    if (blockIdx.x == 0) {
        for (int z = threadIdx.x; z < O5; z += 256) { g_sum[z] = 0.f; g_sq[z] = 0.f; }
    }
    int t = blockIdx.x * 256 + threadIdx.x;
    int o = t % O;
    size_t pn = t / O;
    float sc = g_scale[o], bi = g_bias[o];
    float sel = (sc >= 0.f) ? g_maxv[t] : g_minv[t];
    float y = fmaf(sc, sel, bi);
    float act = (y >= 0.f) ? y : 0.2f * y;
    g_cat[pn * CAT + coff + o] = act;
    if (do_xx) {
        float q = act * act;
#pragma unroll
        for (int s = 16; s; s >>= 1) q += __shfl_xor_sync(0xffffffffu, q, s);
        if ((threadIdx.x & 31) == 0) sq_s[threadIdx.x >> 5] = q;
        __syncthreads();
        int pts = 256 / O, wpp = O / 32;
        if (threadIdx.x < pts) {
            float a = 0.f;
            for (int w = 0; w < wpp; w++) a += sq_s[threadIdx.x * wpp + w];
            g_xx[(size_t)blockIdx.x * pts + threadIdx.x] = a;
        }
    }
}

// -------- final conv1d GEMM: 128x128 tile, 8x8 micro, f32x2, fused n-stats --------
__global__ __launch_bounds__(256, 2) void f1_kernel(const float* __restrict__ W5) {
    __shared__ float Ad[16 * 258];
    __shared__ float Bs_[16 * 132];
    int ob = blockIdx.x * 128;
    int nb = blockIdx.y * 128;
    int b = blockIdx.z;
    int tid = threadIdx.x;
    int tx = tid & 15, ty = tid >> 4;
    const float* cb = g_cat + (size_t)b * NN * CAT;

    ull acc[8][4];
#pragma unroll
    for (int i = 0; i < 8; i++)
#pragma unroll
        for (int j = 0; j < 4; j++) acc[i][j] = 0ull;

    for (int cc = 0; cc < 32; cc++) {
#pragma unroll
        for (int l0 = 0; l0 < 8; l0++) {
            int l = l0 * 256 + tid;
            int c = l & 15, r = l >> 4;
            float a = W5[(size_t)(ob + r) * 512 + (cc << 4) + c];
            float bv = cb[(size_t)(nb + r) * 512 + (cc << 4) + c];
            *(ull*)&Ad[c * 258 + 2 * r] = bcast2(a);
            Bs_[c * 132 + r] = bv;
        }
        __syncthreads();
#pragma unroll
        for (int c = 0; c < 16; c++) {
            const float* arow = &Ad[c * 258 + ty * 16];
            const float* brow = &Bs_[c * 132 + tx * 8];
            ull b0 = *(const ull*)&brow[0];
            ull b1 = *(const ull*)&brow[2];
            ull b2 = *(const ull*)&brow[4];
            ull b3 = *(const ull*)&brow[6];
#pragma unroll
            for (int i = 0; i < 8; i++) {
                ull ap = *(const ull*)&arow[2 * i];
                acc[i][0] = ffma2(ap, b0, acc[i][0]);
                acc[i][1] = ffma2(ap, b1, acc[i][1]);
                acc[i][2] = ffma2(ap, b2, acc[i][2]);
                acc[i][3] = ffma2(ap, b3, acc[i][3]);
            }
        }
        __syncthreads();
    }

#pragma unroll
    for (int i = 0; i < 8; i++) {
        float v[8];
#pragma unroll
        for (int j = 0; j < 4; j++) unpack2(acc[i][j], v[2 * j], v[2 * j + 1]);
        float mx = v[0], mn = v[0], s = v[0], q = v[0] * v[0];
#pragma unroll
        for (int j = 1; j < 8; j++) {
            mx = fmaxf(mx, v[j]);
            mn = fminf(mn, v[j]);
            s += v[j];
            q = fmaf(v[j], v[j], q);
        }
#pragma unroll
        for (int st = 8; st; st >>= 1) {
            mx = fmaxf(mx, __shfl_xor_sync(0xffffffffu, mx, st));
            mn = fminf(mn, __shfl_xor_sync(0xffffffffu, mn, st));
            s += __shfl_xor_sync(0xffffffffu, s, st);
            q += __shfl_xor_sync(0xffffffffu, q, st);
        }
        if (tx == 0) {
            int o = ob + ty * 8 + i;
            g_pmax[((size_t)b * O5 + o) * 8 + blockIdx.y] = mx;
            g_pmin[((size_t)b * O5 + o) * 8 + blockIdx.y] = mn;
            atomicAdd(&g_sum[o], s);
            atomicAdd(&g_sq[o], q);
        }
    }
}

// -------- final BN + lrelu + max over n --------
__global__ void f2_kernel(const float* __restrict__ g5, const float* __restrict__ b5,
                          float* __restrict__ out) {
    int t = blockIdx.x * blockDim.x + threadIdx.x;
    if (t >= BB * O5) return;
    int b = t / O5, o = t % O5;
    float m = g_sum[o] / 8192.f;
    float var = g_sq[o] / 8192.f - m * m;
    float sc = g5[o] * rsqrtf(var + 1e-5f);
    float bi = b5[o] - m * sc;
    size_t base = ((size_t)b * O5 + o) * 8;
    float sel;
    if (sc >= 0.f) {
        sel = g_pmax[base];
        for (int i = 1; i < 8; i++) sel = fmaxf(sel, g_pmax[base + i]);
    } else {
        sel = g_pmin[base];
        for (int i = 1; i < 8; i++) sel = fminf(sel, g_pmin[base + i]);
    }
    float y = fmaf(sc, sel, bi);
    out[t] = (y >= 0.f) ? y : 0.2f * y;
}

extern "C" void kernel_launch(void* const* d_in, const int* in_sizes, int n_in,
                              void* d_out, int out_size) {
    const float* x  = (const float*)d_in[0];
    const float* Wl[4] = {(const float*)d_in[1], (const float*)d_in[4],
                          (const float*)d_in[7], (const float*)d_in[10]};
    const float* gl[4] = {(const float*)d_in[2], (const float*)d_in[5],
                          (const float*)d_in[8], (const float*)d_in[11]};
    const float* bl[4] = {(const float*)d_in[3], (const float*)d_in[6],
                          (const float*)d_in[9], (const float*)d_in[12]};
    const float* W5 = (const float*)d_in[13];
    const float* g5 = (const float*)d_in[14];
    const float* b5 = (const float*)d_in[15];
    float* out = (float*)d_out;

    prep0<<<210, 256>>>(x, Wl[0], Wl[1], Wl[2], Wl[3]);

    const int srcA[4]  = {0, 1, 1, 1};
    const int offA[4]  = {0, 0, 64, 128};
    const int CA[4]    = {3, 64, 64, 128};
    const int OA[4]    = {64, 64, 128, 256};
    const int coffA[4] = {0, 64, 128, 256};
    const int woffA[4] = {0, 256, 4608, 12800};

    for (int L = 0; L < 4; L++) {
        int src = srcA[L], off = offA[L], C = CA[L], O = OA[L], coff = coffA[L];
        int woff = woffA[L];
        int stride = src ? CAT : 4;
        int och = O / 64;
        kd_kernel<<<dim3(36, 1, BB), 256>>>(src, off, stride, C);
        tk2_kernel<<<1024 + 512 * och, 256>>>(src, off, stride, C, O, och, woff);
        k3_kernel<<<dim3(64, BB), 256>>>(gl[L], bl[L], O, 512);
        k4b<<<BB * NN * O / 256, 256>>>(O, coff, (L < 3) ? 1 : 0);
    }

    f1_kernel<<<dim3(8, 8, BB), 256>>>(W5);
    f2_kernel<<<32, 256>>>(g5, b5, out);
}

// round 7
// speedup vs baseline: 1.9674x; 1.0199x over previous
#include <cuda_runtime.h>

#define BB 8
#define NN 1024
#define KK 20
#define CAT 512
#define O5 1024

typedef unsigned long long ull;

__device__ __forceinline__ ull ffma2(ull a, ull b, ull c) {
    ull d;
    asm("fma.rn.f32x2 %0, %1, %2, %3;" : "=l"(d) : "l"(a), "l"(b), "l"(c));
    return d;
}
__device__ __forceinline__ ull bcast2(float v) {
    ull d;
    asm("mov.b64 %0, {%1, %1};" : "=l"(d) : "f"(v));
    return d;
}
__device__ __forceinline__ void unpack2(ull p, float& lo, float& hi) {
    asm("mov.b64 {%0, %1}, %2;" : "=f"(lo), "=f"(hi) : "l"(p));
}

// -------- static device workspaces --------
__device__ float g_f0[BB * NN * 4];
__device__ float g_cat[BB * NN * CAT];
__device__ float g_xx[BB * NN];
__device__ float g_nd[BB * NN * NN];
__device__ int   g_idx[BB * NN * KK];
__device__ float g_v[BB * NN * 256];
__device__ float g_u[BB * NN * 256];
__device__ float g_wa[64 * 1024];
__device__ float g_wu[64 * 1024];
__device__ float g_maxv[BB * NN * 256];
__device__ float g_minv[BB * NN * 256];
__device__ float g_sum[O5];
__device__ float g_sq[O5];
__device__ float g_pmax[BB * O5 * 8];
__device__ float g_pmin[BB * O5 * 8];
__device__ float g_scale[256];
__device__ float g_bias[256];
__device__ int   g_cnt;

__device__ __forceinline__ const float* featPtr(int src, int off) {
    return src ? (g_cat + off) : g_f0;
}

// -------- fused prep: transpose x + xx(layer1) + ALL W splits + zero stats --------
__global__ void prep0(const float* __restrict__ x,
                      const float* __restrict__ W1, const float* __restrict__ W2,
                      const float* __restrict__ W3, const float* __restrict__ W4) {
    int bx = blockIdx.x;
    if (bx < 32) {
        int t = bx * 256 + threadIdx.x;
        int b = t / NN, n = t % NN;
        float x0 = x[(b * 3 + 0) * NN + n];
        float x1 = x[(b * 3 + 1) * NN + n];
        float x2 = x[(b * 3 + 2) * NN + n];
        float* d = g_f0 + (size_t)t * 4;
        d[0] = x0; d[1] = x1; d[2] = x2; d[3] = 0.f;
        float a = fmaf(x0, x0, 0.f);
        a = fmaf(x1, x1, a);
        a = fmaf(x2, x2, a);
        g_xx[t] = a;
    } else if (bx == 32) {
        for (int t = threadIdx.x; t < O5; t += 256) { g_sum[t] = 0.f; g_sq[t] = 0.f; }
    } else {
        int t = (bx - 33) * 256 + threadIdx.x;
        const float* W; int C, O, woff, local;
        if (t < 192)        { W = W1; C = 3;   O = 64;  woff = 0;     local = t; }
        else if (t < 4288)  { W = W2; C = 64;  O = 64;  woff = 256;   local = t - 192; }
        else if (t < 12480) { W = W3; C = 64;  O = 128; woff = 4608;  local = t - 4288; }
        else if (t < 45248) { W = W4; C = 128; O = 256; woff = 12800; local = t - 12480; }
        else return;
        int c = local / O, o = local % O;
        float wa = W[o * (2 * C) + c];
        float wb = W[o * (2 * C) + C + c];
        g_wa[woff + c * O + o] = wa;
        g_wu[woff + c * O + o] = wb - wa;
    }
}

// -------- neg pairwise distance Gram GEMM: symmetric, 128x128 tile, 8x8, f32x2 --------
// A duplicated {a,a}, stride 260 floats (1040B, 16B-aligned rows) -> LDS.128 loads.
__global__ __launch_bounds__(256, 2) void kd_kernel(int src, int off, int stride, int C) {
    __shared__ __align__(16) float Ad[16 * 260];
    __shared__ __align__(16) float Bs_[16 * 132];
    int b = blockIdx.z;
    int bi = 0, rem = blockIdx.x;
    while (rem >= 8 - bi) { rem -= 8 - bi; bi++; }
    int bj = bi + rem;
    int ib = bi * 128, jb = bj * 128;
    int tid = threadIdx.x;
    int tx = tid & 15, ty = tid >> 4;
    const float* fb = featPtr(src, off) + (size_t)b * NN * stride;

    ull acc[8][4];
#pragma unroll
    for (int i = 0; i < 8; i++)
#pragma unroll
        for (int j = 0; j < 4; j++) acc[i][j] = 0ull;

    int nch = (C + 15) >> 4;
    for (int cc = 0; cc < nch; cc++) {
#pragma unroll
        for (int l0 = 0; l0 < 8; l0++) {
            int l = l0 * 256 + tid;
            int c = l & 15, r = l >> 4;
            int cg = (cc << 4) + c;
            float a = 0.f, bv = 0.f;
            if (cg < C) {
                a = fb[(size_t)(ib + r) * stride + cg];
                bv = fb[(size_t)(jb + r) * stride + cg];
            }
            *(ull*)&Ad[c * 260 + 2 * r] = bcast2(a);
            Bs_[c * 132 + r] = bv;
        }
        __syncthreads();
#pragma unroll
        for (int c = 0; c < 16; c++) {
            const float4* arow = (const float4*)&Ad[c * 260 + ty * 16];
            const float4* brow = (const float4*)&Bs_[c * 132 + tx * 8];
            float4 bq0 = brow[0];
            float4 bq1 = brow[1];
            ull b0 = *(ull*)&bq0.x, b1 = *(ull*)&bq0.z;
            ull b2 = *(ull*)&bq1.x, b3 = *(ull*)&bq1.z;
#pragma unroll
            for (int iq = 0; iq < 4; iq++) {
                float4 aq = arow[iq];
                ull a0 = *(ull*)&aq.x;   // {a[2iq], a[2iq]}
                ull a1 = *(ull*)&aq.z;   // {a[2iq+1], a[2iq+1]}
                int i0 = 2 * iq, i1 = 2 * iq + 1;
                acc[i0][0] = ffma2(a0, b0, acc[i0][0]);
                acc[i0][1] = ffma2(a0, b1, acc[i0][1]);
                acc[i0][2] = ffma2(a0, b2, acc[i0][2]);
                acc[i0][3] = ffma2(a0, b3, acc[i0][3]);
                acc[i1][0] = ffma2(a1, b0, acc[i1][0]);
                acc[i1][1] = ffma2(a1, b1, acc[i1][1]);
                acc[i1][2] = ffma2(a1, b2, acc[i1][2]);
                acc[i1][3] = ffma2(a1, b3, acc[i1][3]);
            }
        }
        __syncthreads();
    }

    const float* xxb = g_xx + b * NN;
    float xm[8], xn[8];
#pragma unroll
    for (int j = 0; j < 8; j++) xm[j] = xxb[jb + tx * 8 + j];
#pragma unroll
    for (int i = 0; i < 8; i++) xn[i] = xxb[ib + ty * 8 + i];
    float* nd = g_nd + (size_t)b * NN * NN;

#pragma unroll
    for (int i = 0; i < 8; i++) {
        float v[8];
#pragma unroll
        for (int j = 0; j < 4; j++) unpack2(acc[i][j], v[2 * j], v[2 * j + 1]);
        float4 o0, o1;
        o0.x = 2.f * v[0] - xn[i] - xm[0];
        o0.y = 2.f * v[1] - xn[i] - xm[1];
        o0.z = 2.f * v[2] - xn[i] - xm[2];
        o0.w = 2.f * v[3] - xn[i] - xm[3];
        o1.x = 2.f * v[4] - xn[i] - xm[4];
        o1.y = 2.f * v[5] - xn[i] - xm[5];
        o1.z = 2.f * v[6] - xn[i] - xm[6];
        o1.w = 2.f * v[7] - xn[i] - xm[7];
        float4* dst = (float4*)(nd + (size_t)(ib + ty * 8 + i) * NN + jb + tx * 8);
        dst[0] = o0;
        dst[1] = o1;
    }
    if (bi != bj) {
#pragma unroll
        for (int j = 0; j < 8; j++) {
            float tmp[8];
#pragma unroll
            for (int i = 0; i < 8; i++) {
                float lo, hi;
                unpack2(acc[i][j >> 1], lo, hi);
                float mv = (j & 1) ? hi : lo;
                tmp[i] = 2.f * mv - xn[i] - xm[j];
            }
            float4* d2 = (float4*)(nd + (size_t)(jb + tx * 8 + j) * NN + ib + ty * 8);
            d2[0] = make_float4(tmp[0], tmp[1], tmp[2], tmp[3]);
            d2[1] = make_float4(tmp[4], tmp[5], tmp[6], tmp[7]);
        }
    }
}

__device__ __forceinline__ ull packkey(float v, int gidx) {
    unsigned bb = __float_as_uint(v);
    bb ^= (unsigned)(((int)bb >> 31)) | 0x80000000u;
    return ((ull)bb << 32) | (ull)(1023 - gidx);
}

// -------- fused: top-20 (blocks 0..1023) + v/u GEMM (rest) --------
__global__ __launch_bounds__(256, 4) void tk2_kernel(int src, int off, int stride,
                                                     int C, int O, int och, int woff) {
    __shared__ float sf[16 * 128];
    if (blockIdx.x < 1024) {
        int wid = threadIdx.x >> 5;
        int lane = threadIdx.x & 31;
        int rowg = blockIdx.x * 8 + wid;
        const float* row = g_nd + (size_t)rowg * NN;

        float vals[32];
#pragma unroll
        for (int j = 0; j < 32; j++) vals[j] = row[j * 32 + lane];

        unsigned alive = 0xffffffffu;
        float qv0, qv1, qv2, qv3;
        int qj0, qj1, qj2, qj3;

#define RESCANQ(Q, QV, QJ)                                            \
        {                                                             \
            QV = -3.0e38f; QJ = (Q) * 8;                              \
            _Pragma("unroll")                                         \
            for (int j0 = 0; j0 < 8; j0++) {                          \
                int j = (Q) * 8 + j0;                                 \
                float v = ((alive >> j) & 1u) ? vals[j] : -3.0e38f;   \
                if (v > QV) { QV = v; QJ = j; }                       \
            }                                                         \
        }

        RESCANQ(0, qv0, qj0)
        RESCANQ(1, qv1, qj1)
        RESCANQ(2, qv2, qj2)
        RESCANQ(3, qv3, qj3)

        float lv = qv0; int li = qj0;
        if (qv1 > lv) { lv = qv1; li = qj1; }
        if (qv2 > lv) { lv = qv2; li = qj2; }
        if (qv3 > lv) { lv = qv3; li = qj3; }

        int myout = 0;
        for (int k = 0; k < KK; k++) {
            ull key = packkey(lv, li * 32 + lane);
#pragma unroll
            for (int s = 16; s; s >>= 1) {
                ull ok = __shfl_xor_sync(0xffffffffu, key, s);
                key = (ok > key) ? ok : key;
            }
            int gidx = 1023 - (int)(key & 0xffffffffu);
            if (lane == k) myout = gidx;
            if (lane == (gidx & 31)) {
                int jrem = gidx >> 5;
                alive &= ~(1u << jrem);
                int q = jrem >> 3;
                if (q == 0)      RESCANQ(0, qv0, qj0)
                else if (q == 1) RESCANQ(1, qv1, qj1)
                else if (q == 2) RESCANQ(2, qv2, qj2)
                else             RESCANQ(3, qv3, qj3)
                lv = qv0; li = qj0;
                if (qv1 > lv) { lv = qv1; li = qj1; }
                if (qv2 > lv) { lv = qv2; li = qj2; }
                if (qv3 > lv) { lv = qv3; li = qj3; }
            }
        }
        if (lane < KK) g_idx[rowg * KK + lane] = myout;
#undef RESCANQ
    } else {
        int kb = blockIdx.x - 1024;
        int bpb = 64 * och;
        int b = kb / bpb;
        int rm = kb % bpb;
        int n0 = (rm / och) * 16;
        int o0 = (rm % och) * 64;
        int og = threadIdx.x & 63;
        int pg = threadIdx.x >> 6;
        int o = o0 + og;
        const float* fb = featPtr(src, off) + ((size_t)b * NN + n0) * stride;
        for (int l = threadIdx.x; l < 16 * C; l += 256) {
            int p = l / C, c = l % C;
            sf[p * C + c] = fb[(size_t)p * stride + c];
        }
        __syncthreads();
        float va[4], vu[4];
#pragma unroll
        for (int p = 0; p < 4; p++) { va[p] = 0.f; vu[p] = 0.f; }
        const float* wap = g_wa + woff + o;
        const float* wup = g_wu + woff + o;
        const float* sfp = sf + pg * 4 * C;
        for (int c = 0; c < C; c++) {
            float wa = wap[c * O];
            float wu = wup[c * O];
#pragma unroll
            for (int p = 0; p < 4; p++) {
                float f = sfp[p * C + c];
                va[p] = fmaf(wa, f, va[p]);
                vu[p] = fmaf(wu, f, vu[p]);
            }
        }
#pragma unroll
        for (int p = 0; p < 4; p++) {
            size_t idx = ((size_t)b * NN + n0 + pg * 4 + p) * O + o;
            g_v[idx] = va[p];
            g_u[idx] = vu[p];
        }
    }
}

// -------- gather + k-reduce + channel stats + folded BN finalize --------
// 8-point strips, 256 threads: pp = tid/O lane, o = tid%O; grid (128, BB).
__global__ __launch_bounds__(256, 8) void k3_kernel(const float* __restrict__ gam,
                          const float* __restrict__ bet, int O, int total_blocks) {
    int b = blockIdx.y;
    int n0 = blockIdx.x * 8;
    int o = threadIdx.x % O;
    int pp = threadIdx.x / O;
    int ppl = 256 / O;
    int ppp = 8 / ppl;                   // points per lane
    size_t base = (size_t)b * NN;
    float s = 0.f, q = 0.f;
    for (int p = 0; p < ppp; p++) {
        int n = n0 + pp * ppp + p;
        const int* id = g_idx + (base + n) * KK;
        float uu = g_u[(base + n) * O + o];
        float mx = -3.0e38f, mn = 3.0e38f;
#pragma unroll
        for (int k = 0; k < KK; k++) {
            int j = id[k];
            float y = g_v[(base + j) * O + o] + uu;
            mx = fmaxf(mx, y);
            mn = fminf(mn, y);
            s += y;
            q = fmaf(y, y, q);
        }
        size_t t = (base + n) * O + o;
        g_maxv[t] = mx;
        g_minv[t] = mn;
    }
    atomicAdd(&g_sum[o], s);
    atomicAdd(&g_sq[o], q);

    __threadfence();
    __shared__ int isLast;
    if (threadIdx.x == 0) isLast = (atomicAdd(&g_cnt, 1) == total_blocks - 1);
    __syncthreads();
    if (isLast && threadIdx.x < O) {
        volatile float* vs = g_sum;
        volatile float* vq = g_sq;
        float cnt = (float)(BB * NN * KK);
        float m = vs[o] / cnt;
        float var = vq[o] / cnt - m * m;
        float sc = gam[o] * rsqrtf(var + 1e-5f);
        g_scale[o] = sc;
        g_bias[o] = bet[o] - m * sc;
        if (o == 0) g_cnt = 0;
    }
}

// -------- BN+lrelu apply -> cat ; fused next-layer xx ; zero stats --------
__global__ void k4b(int O, int coff, int do_xx) {
    __shared__ float sq_s[8];
    if (blockIdx.x == 0) {
        for (int z = threadIdx.x; z < O5; z += 256) { g_sum[z] = 0.f; g_sq[z] = 0.f; }
    }
    int t = blockIdx.x * 256 + threadIdx.x;
    int o = t % O;
    size_t pn = t / O;
    float sc = g_scale[o], bi = g_bias[o];
    float sel = (sc >= 0.f) ? g_maxv[t] : g_minv[t];
    float y = fmaf(sc, sel, bi);
    float act = (y >= 0.f) ? y : 0.2f * y;
    g_cat[pn * CAT + coff + o] = act;
    if (do_xx) {
        float q = act * act;
#pragma unroll
        for (int s = 16; s; s >>= 1) q += __shfl_xor_sync(0xffffffffu, q, s);
        if ((threadIdx.x & 31) == 0) sq_s[threadIdx.x >> 5] = q;
        __syncthreads();
        int pts = 256 / O, wpp = O / 32;
        if (threadIdx.x < pts) {
            float a = 0.f;
            for (int w = 0; w < wpp; w++) a += sq_s[threadIdx.x * wpp + w];
            g_xx[(size_t)blockIdx.x * pts + threadIdx.x] = a;
        }
    }
}

// -------- final conv1d GEMM: 128x128 tile, 8x8 micro, f32x2, fused n-stats --------
__global__ __launch_bounds__(256, 2) void f1_kernel(const float* __restrict__ W5) {
    __shared__ __align__(16) float Ad[16 * 260];
    __shared__ __align__(16) float Bs_[16 * 132];
    int ob = blockIdx.x * 128;
    int nb = blockIdx.y * 128;
    int b = blockIdx.z;
    int tid = threadIdx.x;
    int tx = tid & 15, ty = tid >> 4;
    const float* cb = g_cat + (size_t)b * NN * CAT;

    ull acc[8][4];
#pragma unroll
    for (int i = 0; i < 8; i++)
#pragma unroll
        for (int j = 0; j < 4; j++) acc[i][j] = 0ull;

    for (int cc = 0; cc < 32; cc++) {
#pragma unroll
        for (int l0 = 0; l0 < 8; l0++) {
            int l = l0 * 256 + tid;
            int c = l & 15, r = l >> 4;
            float a = W5[(size_t)(ob + r) * 512 + (cc << 4) + c];
            float bv = cb[(size_t)(nb + r) * 512 + (cc << 4) + c];
            *(ull*)&Ad[c * 260 + 2 * r] = bcast2(a);
            Bs_[c * 132 + r] = bv;
        }
        __syncthreads();
#pragma unroll
        for (int c = 0; c < 16; c++) {
            const float4* arow = (const float4*)&Ad[c * 260 + ty * 16];
            const float4* brow = (const float4*)&Bs_[c * 132 + tx * 8];
            float4 bq0 = brow[0];
            float4 bq1 = brow[1];
            ull b0 = *(ull*)&bq0.x, b1 = *(ull*)&bq0.z;
            ull b2 = *(ull*)&bq1.x, b3 = *(ull*)&bq1.z;
#pragma unroll
            for (int iq = 0; iq < 4; iq++) {
                float4 aq = arow[iq];
                ull a0 = *(ull*)&aq.x;
                ull a1 = *(ull*)&aq.z;
                int i0 = 2 * iq, i1 = 2 * iq + 1;
                acc[i0][0] = ffma2(a0, b0, acc[i0][0]);
                acc[i0][1] = ffma2(a0, b1, acc[i0][1]);
                acc[i0][2] = ffma2(a0, b2, acc[i0][2]);
                acc[i0][3] = ffma2(a0, b3, acc[i0][3]);
                acc[i1][0] = ffma2(a1, b0, acc[i1][0]);
                acc[i1][1] = ffma2(a1, b1, acc[i1][1]);
                acc[i1][2] = ffma2(a1, b2, acc[i1][2]);
                acc[i1][3] = ffma2(a1, b3, acc[i1][3]);
            }
        }
        __syncthreads();
    }

#pragma unroll
    for (int i = 0; i < 8; i++) {
        float v[8];
#pragma unroll
        for (int j = 0; j < 4; j++) unpack2(acc[i][j], v[2 * j], v[2 * j + 1]);
        float mx = v[0], mn = v[0], s = v[0], q = v[0] * v[0];
#pragma unroll
        for (int j = 1; j < 8; j++) {
            mx = fmaxf(mx, v[j]);
            mn = fminf(mn, v[j]);
            s += v[j];
            q = fmaf(v[j], v[j], q);
        }
#pragma unroll
        for (int st = 8; st; st >>= 1) {
            mx = fmaxf(mx, __shfl_xor_sync(0xffffffffu, mx, st));
            mn = fminf(mn, __shfl_xor_sync(0xffffffffu, mn, st));
            s += __shfl_xor_sync(0xffffffffu, s, st);
            q += __shfl_xor_sync(0xffffffffu, q, st);
        }
        if (tx == 0) {
            int o = ob + ty * 8 + i;
            g_pmax[((size_t)b * O5 + o) * 8 + blockIdx.y] = mx;
            g_pmin[((size_t)b * O5 + o) * 8 + blockIdx.y] = mn;
            atomicAdd(&g_sum[o], s);
            atomicAdd(&g_sq[o], q);
        }
    }
}

// -------- final BN + lrelu + max over n --------
__global__ void f2_kernel(const float* __restrict__ g5, const float* __restrict__ b5,
                          float* __restrict__ out) {
    int t = blockIdx.x * blockDim.x + threadIdx.x;
    if (t >= BB * O5) return;
    int b = t / O5, o = t % O5;
    float m = g_sum[o] / 8192.f;
    float var = g_sq[o] / 8192.f - m * m;
    float sc = g5[o] * rsqrtf(var + 1e-5f);
    float bi = b5[o] - m * sc;
    size_t base = ((size_t)b * O5 + o) * 8;
    float sel;
    if (sc >= 0.f) {
        sel = g_pmax[base];
        for (int i = 1; i < 8; i++) sel = fmaxf(sel, g_pmax[base + i]);
    } else {
        sel = g_pmin[base];
        for (int i = 1; i < 8; i++) sel = fminf(sel, g_pmin[base + i]);
    }
    float y = fmaf(sc, sel, bi);
    out[t] = (y >= 0.f) ? y : 0.2f * y;
}

extern "C" void kernel_launch(void* const* d_in, const int* in_sizes, int n_in,
                              void* d_out, int out_size) {
    const float* x  = (const float*)d_in[0];
    const float* Wl[4] = {(const float*)d_in[1], (const float*)d_in[4],
                          (const float*)d_in[7], (const float*)d_in[10]};
    const float* gl[4] = {(const float*)d_in[2], (const float*)d_in[5],
                          (const float*)d_in[8], (const float*)d_in[11]};
    const float* bl[4] = {(const float*)d_in[3], (const float*)d_in[6],
                          (const float*)d_in[9], (const float*)d_in[12]};
    const float* W5 = (const float*)d_in[13];
    const float* g5 = (const float*)d_in[14];
    const float* b5 = (const float*)d_in[15];
    float* out = (float*)d_out;

    prep0<<<210, 256>>>(x, Wl[0], Wl[1], Wl[2], Wl[3]);

    const int srcA[4]  = {0, 1, 1, 1};
    const int offA[4]  = {0, 0, 64, 128};
    const int CA[4]    = {3, 64, 64, 128};
    const int OA[4]    = {64, 64, 128, 256};
    const int coffA[4] = {0, 64, 128, 256};
    const int woffA[4] = {0, 256, 4608, 12800};

    for (int L = 0; L < 4; L++) {
        int src = srcA[L], off = offA[L], C = CA[L], O = OA[L], coff = coffA[L];
        int woff = woffA[L];
        int stride = src ? CAT : 4;
        int och = O / 64;
        kd_kernel<<<dim3(36, 1, BB), 256>>>(src, off, stride, C);
        tk2_kernel<<<1024 + 512 * och, 256>>>(src, off, stride, C, O, och, woff);
        k3_kernel<<<dim3(128, BB), 256>>>(gl[L], bl[L], O, 1024);
        k4b<<<BB * NN * O / 256, 256>>>(O, coff, (L < 3) ? 1 : 0);
    }

    f1_kernel<<<dim3(8, 8, BB), 256>>>(W5);
    f2_kernel<<<32, 256>>>(g5, b5, out);
}